// round 2
// baseline (speedup 1.0000x reference)
#include <cuda_runtime.h>
#include <math.h>

// Problem constants (fixed by the dataset)
#define MAXN   100000
#define MAXE   1600000
#define FEAT   128
#define COUT   64

// ---------------------------------------------------------------------------
// Scratch (device globals — no allocations allowed)
// ---------------------------------------------------------------------------
__device__ float g_h [MAXN * FEAT];   // current layer's h = input @ W
__device__ float g_o1[MAXN * FEAT];   // layer-1 output (relu'd in place)
__device__ float g_o2[MAXN * FEAT];   // layer-2 output
__device__ float g_ssrc[MAXN];
__device__ float g_sdst[MAXN];
__device__ float g_m   [MAXN];
__device__ float g_den [MAXN];
__device__ float g_es  [MAXN];
__device__ int   g_edges[2 * MAXE];   // normalized int32 [src(E), dst(E)]
__device__ int   g_is64;

// ---------------------------------------------------------------------------
// Edge dtype detection + normalization
// ---------------------------------------------------------------------------
__global__ void detect_kernel(const void* ei, int n_check, int N) {
    if (threadIdx.x == 0 && blockIdx.x == 0) {
        const long long* p = (const long long*)ei;
        int is64 = 1;
        for (int i = 0; i < n_check; i++) {
            long long v = p[i];
            if (v < 0 || v >= (long long)N) { is64 = 0; break; }
        }
        g_is64 = is64;
    }
}

__global__ void convert_edges(const void* ei, int n) {
    int i = blockIdx.x * blockDim.x + threadIdx.x;
    if (i >= n) return;
    int v;
    if (g_is64) v = (int)((const long long*)ei)[i];
    else        v = ((const int*)ei)[i];
    g_edges[i] = v;
}

// ---------------------------------------------------------------------------
// SGEMM: Hout[N,128] = A[N,128] @ W[128,128]
// BM=64, BN=128, BK=16, TM=8, TN=4, 256 threads
// ---------------------------------------------------------------------------
#define BM 64
#define BN 128
#define BK 16
#define TM 8
#define TN 4

__global__ void sgemm_h(const float* __restrict__ A, const float* __restrict__ W,
                        float* __restrict__ Hout, int N) {
    __shared__ __align__(16) float As[BM][BK];
    __shared__ __align__(16) float Bs[BK][BN];

    int t = threadIdx.x;
    int rowBase = blockIdx.x * BM;
    int trow = (t >> 5) * TM;     // 0..56
    int tcol = (t & 31) * TN;     // 0..124

    float acc[TM][TN];
#pragma unroll
    for (int i = 0; i < TM; i++)
#pragma unroll
        for (int j = 0; j < TN; j++) acc[i][j] = 0.f;

    int ai = t >> 2;           // 0..63
    int aj = (t & 3) * 4;      // 0,4,8,12

    for (int kk = 0; kk < FEAT; kk += BK) {
        // load A tile (64x16)
        float4 av = make_float4(0.f, 0.f, 0.f, 0.f);
        int grow = rowBase + ai;
        if (grow < N) av = *(const float4*)(A + (size_t)grow * FEAT + kk + aj);
        *(float4*)&As[ai][aj] = av;
        // load W chunk (16x128): 512 float4, 2 per thread
#pragma unroll
        for (int v = 0; v < 2; v++) {
            int idx = t + v * 256;
            int kr = idx >> 5;
            int nb = (idx & 31) * 4;
            float4 bv = *(const float4*)(W + (size_t)(kk + kr) * BN + nb);
            *(float4*)&Bs[kr][nb] = bv;
        }
        __syncthreads();
#pragma unroll
        for (int k = 0; k < BK; k++) {
            float b0 = Bs[k][tcol + 0];
            float b1 = Bs[k][tcol + 1];
            float b2 = Bs[k][tcol + 2];
            float b3 = Bs[k][tcol + 3];
#pragma unroll
            for (int i = 0; i < TM; i++) {
                float a = As[trow + i][k];
                acc[i][0] = fmaf(a, b0, acc[i][0]);
                acc[i][1] = fmaf(a, b1, acc[i][1]);
                acc[i][2] = fmaf(a, b2, acc[i][2]);
                acc[i][3] = fmaf(a, b3, acc[i][3]);
            }
        }
        __syncthreads();
    }
#pragma unroll
    for (int i = 0; i < TM; i++) {
        int grow = rowBase + trow + i;
        if (grow < N) {
            float4 o = make_float4(acc[i][0], acc[i][1], acc[i][2], acc[i][3]);
            *(float4*)(Hout + (size_t)grow * FEAT + tcol) = o;
        }
    }
}

// ---------------------------------------------------------------------------
// Per-node scores + self-loop init: warp per node
// ---------------------------------------------------------------------------
__global__ void scores_kernel(const float* __restrict__ h,
                              const float* __restrict__ a_src,
                              const float* __restrict__ a_dst,
                              int N) {
    int warp = (blockIdx.x * blockDim.x + threadIdx.x) >> 5;
    int lane = threadIdx.x & 31;
    if (warp >= N) return;
    float4 hv = *(const float4*)(h + (size_t)warp * FEAT + lane * 4);
    float4 as = *(const float4*)(a_src + lane * 4);
    float4 ad = *(const float4*)(a_dst + lane * 4);
    float s1 = hv.x * as.x + hv.y * as.y + hv.z * as.z + hv.w * as.w;
    float s2 = hv.x * ad.x + hv.y * ad.y + hv.z * ad.z + hv.w * ad.w;
#pragma unroll
    for (int o = 16; o; o >>= 1) {
        s1 += __shfl_down_sync(0xffffffffu, s1, o);
        s2 += __shfl_down_sync(0xffffffffu, s2, o);
    }
    if (lane == 0) {
        g_ssrc[warp] = s1;
        g_sdst[warp] = s2;
        float e = s1 + s2;
        e = e > 0.f ? e : 0.2f * e;     // leaky_relu(slope 0.2)
        g_es[warp] = e;                  // self-loop logit
        g_m[warp]  = e;                  // max init with self-loop
    }
}

__device__ __forceinline__ void atomicMaxF(float* addr, float v) {
    if (v >= 0.f) atomicMax((int*)addr, __float_as_int(v));
    else          atomicMin((unsigned int*)addr, __float_as_uint(v));
}

// ---------------------------------------------------------------------------
// Edge pass 1: segment max
// ---------------------------------------------------------------------------
__global__ void edge_max(int E) {
    int i = blockIdx.x * blockDim.x + threadIdx.x;
    if (i >= E) return;
    int s = g_edges[i];
    int d = g_edges[E + i];
    float e = g_ssrc[s] + g_sdst[d];
    e = e > 0.f ? e : 0.2f * e;
    atomicMaxF(&g_m[d], e);
}

// denom init with self-loop contribution
__global__ void denom_init(int N) {
    int i = blockIdx.x * blockDim.x + threadIdx.x;
    if (i >= N) return;
    g_den[i] = __expf(g_es[i] - g_m[i]);
}

// Edge pass 2: segment sum of exp
__global__ void edge_denom(int E) {
    int i = blockIdx.x * blockDim.x + threadIdx.x;
    if (i >= E) return;
    int s = g_edges[i];
    int d = g_edges[E + i];
    float e = g_ssrc[s] + g_sdst[d];
    e = e > 0.f ? e : 0.2f * e;
    atomicAdd(&g_den[d], __expf(e - g_m[d]));
}

// Per-node output init: out = b + alpha_self * h  (warp per node)
__global__ void node_out_init(const float* __restrict__ h,
                              const float* __restrict__ b,
                              float* __restrict__ out, int N) {
    int warp = (blockIdx.x * blockDim.x + threadIdx.x) >> 5;
    int lane = threadIdx.x & 31;
    if (warp >= N) return;
    float al = __expf(g_es[warp] - g_m[warp]) / g_den[warp];
    float4 hv = *(const float4*)(h + (size_t)warp * FEAT + lane * 4);
    float4 bv = *(const float4*)(b + lane * 4);
    float4 o;
    o.x = fmaf(al, hv.x, bv.x);
    o.y = fmaf(al, hv.y, bv.y);
    o.z = fmaf(al, hv.z, bv.z);
    o.w = fmaf(al, hv.w, bv.w);
    *(float4*)(out + (size_t)warp * FEAT + lane * 4) = o;
}

// Edge pass 3: weighted aggregation (warp per edge)
__global__ void edge_agg(const float* __restrict__ h, float* __restrict__ out, int E) {
    int e = blockIdx.x * 8 + (threadIdx.x >> 5);
    if (e >= E) return;
    int lane = threadIdx.x & 31;
    int s = g_edges[e];
    int d = g_edges[E + e];
    float ev = g_ssrc[s] + g_sdst[d];
    ev = ev > 0.f ? ev : 0.2f * ev;
    float alpha = __expf(ev - g_m[d]) / g_den[d];
    float4 hv = *(const float4*)(h + (size_t)s * FEAT + lane * 4);
    float* o = out + (size_t)d * FEAT + lane * 4;
    atomicAdd(o + 0, alpha * hv.x);
    atomicAdd(o + 1, alpha * hv.y);
    atomicAdd(o + 2, alpha * hv.z);
    atomicAdd(o + 3, alpha * hv.w);
}

__global__ void relu_kernel(float* __restrict__ p, int n) {
    int i = blockIdx.x * blockDim.x + threadIdx.x;
    if (i < n) p[i] = fmaxf(p[i], 0.f);
}

// ---------------------------------------------------------------------------
// Final: y = h1 + h2; logits = y @ Wl + bl; log_softmax
// 256 threads = 4 groups of 64; Wl staged in shared once per block
// ---------------------------------------------------------------------------
__global__ void final_kernel(const float* __restrict__ h1, const float* __restrict__ h2,
                             const float* __restrict__ Wl, const float* __restrict__ bl,
                             float* __restrict__ out, int N) {
    __shared__ float Wls[FEAT * COUT];
    __shared__ float bls[COUT];
    __shared__ float ys[4][FEAT];
    __shared__ float red[4][2];

    int t = threadIdx.x;
    for (int i = t; i < FEAT * COUT; i += 256) Wls[i] = Wl[i];
    if (t < COUT) bls[t] = bl[t];
    int g = t >> 6;
    int c = t & 63;
    int wing = (t >> 5) & 1;

    for (int base = blockIdx.x * 4; base < N; base += gridDim.x * 4) {
        int node = base + g;
        bool act = node < N;
        __syncthreads();                 // Wls ready (1st iter) / ys reuse safe
        if (act) {
            const float* p1 = h1 + (size_t)node * FEAT;
            const float* p2 = h2 + (size_t)node * FEAT;
            ys[g][c]      = p1[c]      + p2[c];
            ys[g][c + 64] = p1[c + 64] + p2[c + 64];
        }
        __syncthreads();
        float acc = bls[c];
#pragma unroll 16
        for (int k = 0; k < FEAT; k++)
            acc = fmaf(ys[g][k], Wls[k * COUT + c], acc);

        float mx = acc;
#pragma unroll
        for (int o = 16; o; o >>= 1) mx = fmaxf(mx, __shfl_xor_sync(0xffffffffu, mx, o));
        if ((t & 31) == 0) red[g][wing] = mx;
        __syncthreads();
        mx = fmaxf(red[g][0], red[g][1]);
        __syncthreads();
        float sm = expf(acc - mx);
#pragma unroll
        for (int o = 16; o; o >>= 1) sm += __shfl_xor_sync(0xffffffffu, sm, o);
        if ((t & 31) == 0) red[g][wing] = sm;
        __syncthreads();
        sm = red[g][0] + red[g][1];
        if (act) out[(size_t)node * COUT + c] = acc - mx - logf(sm);
    }
}

// Optional extra output: edge_index appended as float
__global__ void copy_edges_float(const void* ei, float* o, int n) {
    int i = blockIdx.x * blockDim.x + threadIdx.x;
    if (i >= n) return;
    long long v = g_is64 ? ((const long long*)ei)[i]
                         : (long long)((const int*)ei)[i];
    o[i] = (float)v;
}

// ---------------------------------------------------------------------------
// Host orchestration
// ---------------------------------------------------------------------------
static void run_layer(const float* input, const float* W, const float* a_s,
                      const float* a_d, const float* b,
                      float* h, float* out, int N, int E) {
    sgemm_h<<<(N + BM - 1) / BM, 256>>>(input, W, h, N);
    scores_kernel<<<(N + 7) / 8, 256>>>(h, a_s, a_d, N);
    edge_max<<<(E + 255) / 256, 256>>>(E);
    denom_init<<<(N + 255) / 256, 256>>>(N);
    edge_denom<<<(E + 255) / 256, 256>>>(E);
    node_out_init<<<(N + 7) / 8, 256>>>(h, b, out, N);
    edge_agg<<<(E + 7) / 8, 256>>>(h, out, E);
}

extern "C" void kernel_launch(void* const* d_in, const int* in_sizes, int n_in,
                              void* d_out, int out_size) {
    const float* x   = (const float*)d_in[0];
    const void*  ei  = d_in[1];
    const float* W1  = (const float*)d_in[2];
    const float* a1s = (const float*)d_in[3];
    const float* a1d = (const float*)d_in[4];
    const float* b1  = (const float*)d_in[5];
    const float* W2  = (const float*)d_in[6];
    const float* a2s = (const float*)d_in[7];
    const float* a2d = (const float*)d_in[8];
    const float* b2  = (const float*)d_in[9];
    const float* Wl  = (const float*)d_in[10];
    const float* bl  = (const float*)d_in[11];

    int N = in_sizes[0] / FEAT;
    int E = in_sizes[1] / 2;

    float *h, *o1, *o2;
    cudaGetSymbolAddress((void**)&h,  g_h);
    cudaGetSymbolAddress((void**)&o1, g_o1);
    cudaGetSymbolAddress((void**)&o2, g_o2);

    // normalize edge indices to int32
    int ncheck = (2 * E < 2048) ? 2 * E : 2048;
    detect_kernel<<<1, 1>>>(ei, ncheck, N);
    convert_edges<<<(2 * E + 255) / 256, 256>>>(ei, 2 * E);

    // layer 1: h1 = relu(gat(x))
    run_layer(x, W1, a1s, a1d, b1, h, o1, N, E);
    relu_kernel<<<(N * FEAT + 255) / 256, 256>>>(o1, N * FEAT);

    // layer 2: h2 = gat(h1)
    run_layer(o1, W2, a2s, a2d, b2, h, o2, N, E);

    // final: log_softmax((h1 + h2) @ Wl + bl)
    int fgrid = (N + 3) / 4;
    if (fgrid > 888) fgrid = 888;
    final_kernel<<<fgrid, 256>>>(o1, o2, Wl, bl, (float*)d_out, N);

    // append edge_index if the output buffer expects the full tuple
    long long extra = (long long)out_size - (long long)N * COUT;
    if (extra == 2LL * E) {
        copy_edges_float<<<(2 * E + 255) / 256, 256>>>(ei, (float*)d_out + (size_t)N * COUT, 2 * E);
    } else if (extra == 4LL * E) {
        cudaMemcpyAsync((char*)d_out + (size_t)N * COUT * sizeof(float), ei,
                        sizeof(long long) * 2 * E, cudaMemcpyDeviceToDevice);
    }
}

// round 3
// speedup vs baseline: 2.5270x; 2.5270x over previous
#include <cuda_runtime.h>
#include <math.h>

#define MAXN   100000
#define MAXE   1600000
#define FEAT   128
#define COUT   64

// ---------------------------------------------------------------------------
// Scratch (device globals — no allocations allowed)
// ---------------------------------------------------------------------------
__device__ float g_h [MAXN * FEAT];
__device__ float g_o1[MAXN * FEAT];
__device__ float g_o2[MAXN * FEAT];
__device__ float g_ssrc[MAXN];
__device__ float g_sdst[MAXN];
__device__ float g_es  [MAXN];
__device__ int   g_edges[2 * MAXE];    // int32 [src(E), dst(E)]
__device__ int   g_rowptr[MAXN + 1];   // CSR by dst
__device__ int   g_csr_src[MAXE];
__device__ int   g_deg [MAXN];
__device__ int   g_fill[MAXN];
__device__ int   g_boff[256];
__device__ int   g_is64;

// ---------------------------------------------------------------------------
// Edge dtype detection + normalization
// ---------------------------------------------------------------------------
__global__ void detect_kernel(const void* ei, int n_check, int N) {
    if (threadIdx.x == 0 && blockIdx.x == 0) {
        const long long* p = (const long long*)ei;
        int is64 = 1;
        for (int i = 0; i < n_check; i++) {
            long long v = p[i];
            if (v < 0 || v >= (long long)N) { is64 = 0; break; }
        }
        g_is64 = is64;
    }
}

__global__ void convert_edges(const void* ei, int n) {
    int i = blockIdx.x * blockDim.x + threadIdx.x;
    if (i >= n) return;
    int v;
    if (g_is64) v = (int)((const long long*)ei)[i];
    else        v = ((const int*)ei)[i];
    g_edges[i] = v;
}

// ---------------------------------------------------------------------------
// CSR build (by destination)
// ---------------------------------------------------------------------------
__global__ void deg_zero(int N) {
    int i = blockIdx.x * blockDim.x + threadIdx.x;
    if (i < N) { g_deg[i] = 0; g_fill[i] = 0; }
}

__global__ void deg_count(int E) {
    int i = blockIdx.x * blockDim.x + threadIdx.x;
    if (i >= E) return;
    atomicAdd(&g_deg[g_edges[E + i]], 1);
}

#define SCAN_B 1024
__global__ void scan_blocks(int N) {
    __shared__ int sh[SCAN_B];
    int tid = threadIdx.x;
    int i = blockIdx.x * SCAN_B + tid;
    int v = (i < N) ? g_deg[i] : 0;
    sh[tid] = v;
    __syncthreads();
#pragma unroll
    for (int o = 1; o < SCAN_B; o <<= 1) {
        int t = (tid >= o) ? sh[tid - o] : 0;
        __syncthreads();
        sh[tid] += t;
        __syncthreads();
    }
    if (i < N) g_rowptr[i] = sh[tid] - v;          // block-local exclusive
    if (tid == SCAN_B - 1) g_boff[blockIdx.x] = sh[tid];
}

__global__ void scan_bsums(int nb) {
    if (threadIdx.x == 0 && blockIdx.x == 0) {
        int run = 0;
        for (int b = 0; b < nb; b++) {
            int v = g_boff[b];
            g_boff[b] = run;
            run += v;
        }
    }
}

__global__ void add_offsets(int N, int E) {
    int i = blockIdx.x * blockDim.x + threadIdx.x;
    if (i < N) g_rowptr[i] += g_boff[i >> 10];
    if (i == 0) g_rowptr[N] = E;
}

__global__ void csr_fill(int E) {
    int i = blockIdx.x * blockDim.x + threadIdx.x;
    if (i >= E) return;
    int d = g_edges[E + i];
    int pos = g_rowptr[d] + atomicAdd(&g_fill[d], 1);
    g_csr_src[pos] = g_edges[i];
}

// ---------------------------------------------------------------------------
// SGEMM with fused attention scores: Hout = A @ W; s_src/s_dst/e_self per row
// BM=64, BN=128, BK=16, TM=8, TN=4, 256 threads
// ---------------------------------------------------------------------------
#define BM 64
#define BN 128
#define BK 16
#define TM 8
#define TN 4

__global__ void sgemm_scores(const float* __restrict__ A, const float* __restrict__ W,
                             const float* __restrict__ a_src, const float* __restrict__ a_dst,
                             float* __restrict__ Hout, int N) {
    __shared__ __align__(16) float As[BM][BK];
    __shared__ __align__(16) float Bs[BK][BN];

    int t = threadIdx.x;
    int rowBase = blockIdx.x * BM;
    int trow = (t >> 5) * TM;
    int lane = t & 31;
    int tcol = lane * TN;

    float acc[TM][TN];
#pragma unroll
    for (int i = 0; i < TM; i++)
#pragma unroll
        for (int j = 0; j < TN; j++) acc[i][j] = 0.f;

    int ai = t >> 2;
    int aj = (t & 3) * 4;

    for (int kk = 0; kk < FEAT; kk += BK) {
        float4 av = make_float4(0.f, 0.f, 0.f, 0.f);
        int grow = rowBase + ai;
        if (grow < N) av = *(const float4*)(A + (size_t)grow * FEAT + kk + aj);
        *(float4*)&As[ai][aj] = av;
#pragma unroll
        for (int v = 0; v < 2; v++) {
            int idx = t + v * 256;
            int kr = idx >> 5;
            int nb = (idx & 31) * 4;
            *(float4*)&Bs[kr][nb] = *(const float4*)(W + (size_t)(kk + kr) * BN + nb);
        }
        __syncthreads();
#pragma unroll
        for (int k = 0; k < BK; k++) {
            float b0 = Bs[k][tcol + 0];
            float b1 = Bs[k][tcol + 1];
            float b2 = Bs[k][tcol + 2];
            float b3 = Bs[k][tcol + 3];
#pragma unroll
            for (int i = 0; i < TM; i++) {
                float a = As[trow + i][k];
                acc[i][0] = fmaf(a, b0, acc[i][0]);
                acc[i][1] = fmaf(a, b1, acc[i][1]);
                acc[i][2] = fmaf(a, b2, acc[i][2]);
                acc[i][3] = fmaf(a, b3, acc[i][3]);
            }
        }
        __syncthreads();
    }

    float4 asv = ((const float4*)a_src)[lane];
    float4 adv = ((const float4*)a_dst)[lane];

#pragma unroll
    for (int i = 0; i < TM; i++) {
        int grow = rowBase + trow + i;
        if (grow < N) {
            float4 o = make_float4(acc[i][0], acc[i][1], acc[i][2], acc[i][3]);
            *(float4*)(Hout + (size_t)grow * FEAT + tcol) = o;
        }
        float p1 = acc[i][0] * asv.x + acc[i][1] * asv.y + acc[i][2] * asv.z + acc[i][3] * asv.w;
        float p2 = acc[i][0] * adv.x + acc[i][1] * adv.y + acc[i][2] * adv.z + acc[i][3] * adv.w;
#pragma unroll
        for (int o = 16; o; o >>= 1) {
            p1 += __shfl_xor_sync(0xffffffffu, p1, o);
            p2 += __shfl_xor_sync(0xffffffffu, p2, o);
        }
        if (lane == 0 && grow < N) {
            g_ssrc[grow] = p1;
            g_sdst[grow] = p2;
            float e = p1 + p2;
            g_es[grow] = e > 0.f ? e : 0.2f * e;
        }
    }
}

// ---------------------------------------------------------------------------
// Fused per-node GAT: softmax over incoming edges + weighted aggregation.
// Warp per destination node. No float atomics.
// ---------------------------------------------------------------------------
__global__ void node_gat(const float* __restrict__ h, const float* __restrict__ bias,
                         float* __restrict__ out, int N, int do_relu) {
    int d = (blockIdx.x * blockDim.x + threadIdx.x) >> 5;
    int lane = threadIdx.x & 31;
    if (d >= N) return;

    int beg = g_rowptr[d];
    int end = g_rowptr[d + 1];
    float sdst_d = g_sdst[d];
    float eself = g_es[d];

    // pass 1: segment max (self-loop included)
    float m = eself;
    for (int j = beg + lane; j < end; j += 32) {
        float e = g_ssrc[g_csr_src[j]] + sdst_d;
        e = e > 0.f ? e : 0.2f * e;
        m = fmaxf(m, e);
    }
#pragma unroll
    for (int o = 16; o; o >>= 1) m = fmaxf(m, __shfl_xor_sync(0xffffffffu, m, o));

    // pass 2: denom
    float den = 0.f;
    for (int j = beg + lane; j < end; j += 32) {
        float e = g_ssrc[g_csr_src[j]] + sdst_d;
        e = e > 0.f ? e : 0.2f * e;
        den += __expf(e - m);
    }
#pragma unroll
    for (int o = 16; o; o >>= 1) den += __shfl_xor_sync(0xffffffffu, den, o);
    float aself = __expf(eself - m);
    den += aself;
    float invden = 1.f / den;

    // pass 3: aggregation (all lanes cooperate on 128 features per edge)
    float4 bv = ((const float4*)bias)[lane];
    float4 hv = *(const float4*)(h + (size_t)d * FEAT + lane * 4);
    float a0 = aself * invden;
    float4 acc;
    acc.x = fmaf(a0, hv.x, bv.x);
    acc.y = fmaf(a0, hv.y, bv.y);
    acc.z = fmaf(a0, hv.z, bv.z);
    acc.w = fmaf(a0, hv.w, bv.w);

#pragma unroll 2
    for (int j = beg; j < end; j++) {
        int s = g_csr_src[j];
        float e = g_ssrc[s] + sdst_d;
        e = e > 0.f ? e : 0.2f * e;
        float a = __expf(e - m) * invden;
        float4 v = *(const float4*)(h + (size_t)s * FEAT + lane * 4);
        acc.x = fmaf(a, v.x, acc.x);
        acc.y = fmaf(a, v.y, acc.y);
        acc.z = fmaf(a, v.z, acc.z);
        acc.w = fmaf(a, v.w, acc.w);
    }

    if (do_relu) {
        acc.x = fmaxf(acc.x, 0.f);
        acc.y = fmaxf(acc.y, 0.f);
        acc.z = fmaxf(acc.z, 0.f);
        acc.w = fmaxf(acc.w, 0.f);
    }
    *(float4*)(out + (size_t)d * FEAT + lane * 4) = acc;
}

// ---------------------------------------------------------------------------
// Final: y = h1 + h2; logits = y @ Wl + bl; log_softmax
// ---------------------------------------------------------------------------
__global__ void final_kernel(const float* __restrict__ h1, const float* __restrict__ h2,
                             const float* __restrict__ Wl, const float* __restrict__ bl,
                             float* __restrict__ out, int N) {
    __shared__ float Wls[FEAT * COUT];
    __shared__ float bls[COUT];
    __shared__ float ys[4][FEAT];
    __shared__ float red[4][2];

    int t = threadIdx.x;
    for (int i = t; i < FEAT * COUT; i += 256) Wls[i] = Wl[i];
    if (t < COUT) bls[t] = bl[t];
    int g = t >> 6;
    int c = t & 63;
    int wing = (t >> 5) & 1;

    for (int base = blockIdx.x * 4; base < N; base += gridDim.x * 4) {
        int node = base + g;
        bool act = node < N;
        __syncthreads();
        if (act) {
            const float* p1 = h1 + (size_t)node * FEAT;
            const float* p2 = h2 + (size_t)node * FEAT;
            ys[g][c]      = p1[c]      + p2[c];
            ys[g][c + 64] = p1[c + 64] + p2[c + 64];
        }
        __syncthreads();
        float acc = bls[c];
#pragma unroll 16
        for (int k = 0; k < FEAT; k++)
            acc = fmaf(ys[g][k], Wls[k * COUT + c], acc);

        float mx = acc;
#pragma unroll
        for (int o = 16; o; o >>= 1) mx = fmaxf(mx, __shfl_xor_sync(0xffffffffu, mx, o));
        if ((t & 31) == 0) red[g][wing] = mx;
        __syncthreads();
        mx = fmaxf(red[g][0], red[g][1]);
        __syncthreads();
        float sm = expf(acc - mx);
#pragma unroll
        for (int o = 16; o; o >>= 1) sm += __shfl_xor_sync(0xffffffffu, sm, o);
        if ((t & 31) == 0) red[g][wing] = sm;
        __syncthreads();
        sm = red[g][0] + red[g][1];
        if (act) out[(size_t)node * COUT + c] = acc - mx - logf(sm);
    }
}

__global__ void copy_edges_float(const void* ei, float* o, int n) {
    int i = blockIdx.x * blockDim.x + threadIdx.x;
    if (i >= n) return;
    long long v = g_is64 ? ((const long long*)ei)[i]
                         : (long long)((const int*)ei)[i];
    o[i] = (float)v;
}

// ---------------------------------------------------------------------------
// Host orchestration
// ---------------------------------------------------------------------------
extern "C" void kernel_launch(void* const* d_in, const int* in_sizes, int n_in,
                              void* d_out, int out_size) {
    const float* x   = (const float*)d_in[0];
    const void*  ei  = d_in[1];
    const float* W1  = (const float*)d_in[2];
    const float* a1s = (const float*)d_in[3];
    const float* a1d = (const float*)d_in[4];
    const float* b1  = (const float*)d_in[5];
    const float* W2  = (const float*)d_in[6];
    const float* a2s = (const float*)d_in[7];
    const float* a2d = (const float*)d_in[8];
    const float* b2  = (const float*)d_in[9];
    const float* Wl  = (const float*)d_in[10];
    const float* bl  = (const float*)d_in[11];

    int N = in_sizes[0] / FEAT;
    int E = in_sizes[1] / 2;

    float *h, *o1, *o2;
    cudaGetSymbolAddress((void**)&h,  g_h);
    cudaGetSymbolAddress((void**)&o1, g_o1);
    cudaGetSymbolAddress((void**)&o2, g_o2);

    // edge normalization + CSR build (once; structure shared by both layers)
    int ncheck = (2 * E < 2048) ? 2 * E : 2048;
    detect_kernel<<<1, 1>>>(ei, ncheck, N);
    convert_edges<<<(2 * E + 255) / 256, 256>>>(ei, 2 * E);
    deg_zero<<<(N + 255) / 256, 256>>>(N);
    deg_count<<<(E + 255) / 256, 256>>>(E);
    int nb = (N + SCAN_B - 1) / SCAN_B;
    scan_blocks<<<nb, SCAN_B>>>(N);
    scan_bsums<<<1, 32>>>(nb);
    add_offsets<<<(N + 255) / 256, 256>>>(N, E);
    csr_fill<<<(E + 255) / 256, 256>>>(E);

    // layer 1: h1 = relu(gat(x))
    sgemm_scores<<<(N + BM - 1) / BM, 256>>>(x, W1, a1s, a1d, h, N);
    node_gat<<<(N * 32 + 255) / 256, 256>>>(h, b1, o1, N, 1);

    // layer 2: h2 = gat(h1)
    sgemm_scores<<<(N + BM - 1) / BM, 256>>>(o1, W2, a2s, a2d, h, N);
    node_gat<<<(N * 32 + 255) / 256, 256>>>(h, b2, o2, N, 0);

    // final: log_softmax((h1 + h2) @ Wl + bl)
    int fgrid = (N + 3) / 4;
    if (fgrid > 888) fgrid = 888;
    final_kernel<<<fgrid, 256>>>(o1, o2, Wl, bl, (float*)d_out, N);

    long long extra = (long long)out_size - (long long)N * COUT;
    if (extra == 2LL * E) {
        copy_edges_float<<<(2 * E + 255) / 256, 256>>>(ei, (float*)d_out + (size_t)N * COUT, 2 * E);
    } else if (extra == 4LL * E) {
        cudaMemcpyAsync((char*)d_out + (size_t)N * COUT * sizeof(float), ei,
                        sizeof(long long) * 2 * E, cudaMemcpyDeviceToDevice);
    }
}

// round 4
// speedup vs baseline: 3.0495x; 1.2068x over previous
#include <cuda_runtime.h>
#include <math.h>
#include <stdint.h>

#define MAXN   100000
#define MAXE   1600000
#define FEAT   128
#define COUT   64

// ---------------------------------------------------------------------------
// Scratch (device globals — no allocations allowed)
// ---------------------------------------------------------------------------
__device__ float g_h [MAXN * FEAT];
__device__ float g_o1[MAXN * FEAT];
__device__ float g_o2[MAXN * FEAT];
__device__ float g_ssrc[MAXN];
__device__ float g_sdst[MAXN];
__device__ float g_es  [MAXN];
__device__ int   g_edges[2 * MAXE];    // int32 [src(E), dst(E)]
__device__ int   g_rowptr[MAXN + 1];   // CSR by dst
__device__ int   g_csr_src[MAXE];
__device__ int   g_deg [MAXN];
__device__ int   g_fill[MAXN];
__device__ int   g_boff[256];
__device__ int   g_is64;

// ---------------------------------------------------------------------------
// Edge dtype detection + normalization (+ fused degree count)
// ---------------------------------------------------------------------------
__global__ void detect_kernel(const void* ei, int n_check, int N) {
    if (threadIdx.x == 0 && blockIdx.x == 0) {
        const long long* p = (const long long*)ei;
        int is64 = 1;
        for (int i = 0; i < n_check; i++) {
            long long v = p[i];
            if (v < 0 || v >= (long long)N) { is64 = 0; break; }
        }
        g_is64 = is64;
    }
}

__global__ void convert_count(const void* ei, int E) {
    int i = blockIdx.x * blockDim.x + threadIdx.x;
    if (i >= 2 * E) return;
    int v;
    if (g_is64) v = (int)((const long long*)ei)[i];
    else        v = ((const int*)ei)[i];
    g_edges[i] = v;
    if (i >= E) atomicAdd(&g_deg[v], 1);   // dst half → degree count
}

__global__ void deg_zero(int N) {
    int i = blockIdx.x * blockDim.x + threadIdx.x;
    if (i < N) { g_deg[i] = 0; g_fill[i] = 0; }
}

#define SCAN_B 1024
__global__ void scan_blocks(int N) {
    __shared__ int sh[SCAN_B];
    int tid = threadIdx.x;
    int i = blockIdx.x * SCAN_B + tid;
    int v = (i < N) ? g_deg[i] : 0;
    sh[tid] = v;
    __syncthreads();
#pragma unroll
    for (int o = 1; o < SCAN_B; o <<= 1) {
        int t = (tid >= o) ? sh[tid - o] : 0;
        __syncthreads();
        sh[tid] += t;
        __syncthreads();
    }
    if (i < N) g_rowptr[i] = sh[tid] - v;
    if (tid == SCAN_B - 1) g_boff[blockIdx.x] = sh[tid];
}

__global__ void scan_bsums(int nb) {
    if (threadIdx.x == 0 && blockIdx.x == 0) {
        int run = 0;
        for (int b = 0; b < nb; b++) {
            int v = g_boff[b];
            g_boff[b] = run;
            run += v;
        }
    }
}

__global__ void add_offsets(int N, int E) {
    int i = blockIdx.x * blockDim.x + threadIdx.x;
    if (i < N) g_rowptr[i] += g_boff[i >> 10];
    if (i == 0) g_rowptr[N] = E;
}

__global__ void csr_fill(int E) {
    int i = blockIdx.x * blockDim.x + threadIdx.x;
    if (i >= E) return;
    int d = g_edges[E + i];
    int pos = g_rowptr[d] + atomicAdd(&g_fill[d], 1);
    g_csr_src[pos] = g_edges[i];
}

// ---------------------------------------------------------------------------
// tf32 tensor-core GEMM: H[N,128] = A[N,128] @ W[128,128]
// CTA tile 128x128x32, 8 warps in 4(M)x2(N), warp tile 32x64
// mma.sync.m16n8k8 tf32, fp32 accumulate
// ---------------------------------------------------------------------------
#define GBM 128
#define GBK 32
#define APAD 36
#define BPAD 132

__device__ __forceinline__ uint32_t f2tf32(float f) {
    uint32_t u;
    asm("cvt.rna.tf32.f32 %0, %1;" : "=r"(u) : "f"(f));
    return u;
}

__device__ __forceinline__ void mma_tf32(float4& c, const uint32_t a[4], const uint32_t b[2]) {
    asm volatile(
        "mma.sync.aligned.m16n8k8.row.col.f32.tf32.tf32.f32 "
        "{%0,%1,%2,%3}, {%4,%5,%6,%7}, {%8,%9}, {%0,%1,%2,%3};\n"
        : "+f"(c.x), "+f"(c.y), "+f"(c.z), "+f"(c.w)
        : "r"(a[0]), "r"(a[1]), "r"(a[2]), "r"(a[3]), "r"(b[0]), "r"(b[1]));
}

__global__ void __launch_bounds__(256, 2)
gemm_tf32(const float* __restrict__ A, const float* __restrict__ W,
          float* __restrict__ H, int N) {
    __shared__ uint32_t As[GBM][APAD];
    __shared__ uint32_t Bs[GBK][BPAD];

    int t = threadIdx.x;
    int wid = t >> 5, lane = t & 31;
    int wm = wid >> 1, wn = wid & 1;          // 4(M) x 2(N)
    int rowBase = blockIdx.x * GBM;
    int lg = lane >> 2;                        // group id 0..7
    int lt = lane & 3;                         // thread-in-group 0..3

    float4 c[2][8];
#pragma unroll
    for (int mt = 0; mt < 2; mt++)
#pragma unroll
        for (int nt = 0; nt < 8; nt++) c[mt][nt] = make_float4(0.f, 0.f, 0.f, 0.f);

    int arow = t >> 3;             // 0..31 (step +32 per v)
    int acol = (t & 7) * 4;        // 0..28
    int brow = t >> 5;             // 0..7 (step +8 per v)
    int bcol = lane * 4;           // 0..124

    for (int kk = 0; kk < FEAT; kk += GBK) {
#pragma unroll
        for (int v = 0; v < 4; v++) {
            int r = arow + v * 32;
            int gr = rowBase + r;
            float4 av = make_float4(0.f, 0.f, 0.f, 0.f);
            if (gr < N) av = *(const float4*)(A + (size_t)gr * FEAT + kk + acol);
            As[r][acol + 0] = f2tf32(av.x);
            As[r][acol + 1] = f2tf32(av.y);
            As[r][acol + 2] = f2tf32(av.z);
            As[r][acol + 3] = f2tf32(av.w);
        }
#pragma unroll
        for (int v = 0; v < 4; v++) {
            int r = brow + v * 8;
            float4 wv = *(const float4*)(W + (size_t)(kk + r) * FEAT + bcol);
            Bs[r][bcol + 0] = f2tf32(wv.x);
            Bs[r][bcol + 1] = f2tf32(wv.y);
            Bs[r][bcol + 2] = f2tf32(wv.z);
            Bs[r][bcol + 3] = f2tf32(wv.w);
        }
        __syncthreads();

#pragma unroll
        for (int ks = 0; ks < 4; ks++) {
            int k0 = ks * 8;
            uint32_t af[2][4];
#pragma unroll
            for (int mt = 0; mt < 2; mt++) {
                int row = wm * 32 + mt * 16 + lg;
                af[mt][0] = As[row][k0 + lt];
                af[mt][1] = As[row + 8][k0 + lt];
                af[mt][2] = As[row][k0 + lt + 4];
                af[mt][3] = As[row + 8][k0 + lt + 4];
            }
            uint32_t bf[8][2];
#pragma unroll
            for (int nt = 0; nt < 8; nt++) {
                int col = wn * 64 + nt * 8 + lg;
                bf[nt][0] = Bs[k0 + lt][col];
                bf[nt][1] = Bs[k0 + lt + 4][col];
            }
#pragma unroll
            for (int mt = 0; mt < 2; mt++)
#pragma unroll
                for (int nt = 0; nt < 8; nt++)
                    mma_tf32(c[mt][nt], af[mt], bf[nt]);
        }
        __syncthreads();
    }

    // epilogue
#pragma unroll
    for (int mt = 0; mt < 2; mt++) {
        int row0 = rowBase + wm * 32 + mt * 16 + lg;
#pragma unroll
        for (int nt = 0; nt < 8; nt++) {
            int col = wn * 64 + nt * 8 + lt * 2;
            if (row0 < N)
                *(float2*)(H + (size_t)row0 * FEAT + col) = make_float2(c[mt][nt].x, c[mt][nt].y);
            if (row0 + 8 < N)
                *(float2*)(H + (size_t)(row0 + 8) * FEAT + col) = make_float2(c[mt][nt].z, c[mt][nt].w);
        }
    }
}

// ---------------------------------------------------------------------------
// Per-node attention scores (warp per node)
// ---------------------------------------------------------------------------
__global__ void scores_kernel(const float* __restrict__ h,
                              const float* __restrict__ a_src,
                              const float* __restrict__ a_dst,
                              int N) {
    int warp = (blockIdx.x * blockDim.x + threadIdx.x) >> 5;
    int lane = threadIdx.x & 31;
    if (warp >= N) return;
    float4 hv = *(const float4*)(h + (size_t)warp * FEAT + lane * 4);
    float4 as = ((const float4*)a_src)[lane];
    float4 ad = ((const float4*)a_dst)[lane];
    float s1 = hv.x * as.x + hv.y * as.y + hv.z * as.z + hv.w * as.w;
    float s2 = hv.x * ad.x + hv.y * ad.y + hv.z * ad.z + hv.w * ad.w;
#pragma unroll
    for (int o = 16; o; o >>= 1) {
        s1 += __shfl_down_sync(0xffffffffu, s1, o);
        s2 += __shfl_down_sync(0xffffffffu, s2, o);
    }
    if (lane == 0) {
        g_ssrc[warp] = s1;
        g_sdst[warp] = s2;
        float e = s1 + s2;
        g_es[warp] = e > 0.f ? e : 0.2f * e;
    }
}

// ---------------------------------------------------------------------------
// Fused per-node GAT softmax + aggregation (warp per node, no float atomics)
// ---------------------------------------------------------------------------
__global__ void node_gat(const float* __restrict__ h, const float* __restrict__ bias,
                         float* __restrict__ out, int N, int do_relu) {
    int d = (blockIdx.x * blockDim.x + threadIdx.x) >> 5;
    int lane = threadIdx.x & 31;
    if (d >= N) return;

    int beg = g_rowptr[d];
    int end = g_rowptr[d + 1];
    float sdst_d = g_sdst[d];
    float eself = g_es[d];

    float m = eself;
    for (int j = beg + lane; j < end; j += 32) {
        float e = g_ssrc[g_csr_src[j]] + sdst_d;
        e = e > 0.f ? e : 0.2f * e;
        m = fmaxf(m, e);
    }
#pragma unroll
    for (int o = 16; o; o >>= 1) m = fmaxf(m, __shfl_xor_sync(0xffffffffu, m, o));

    float den = 0.f;
    for (int j = beg + lane; j < end; j += 32) {
        float e = g_ssrc[g_csr_src[j]] + sdst_d;
        e = e > 0.f ? e : 0.2f * e;
        den += __expf(e - m);
    }
#pragma unroll
    for (int o = 16; o; o >>= 1) den += __shfl_xor_sync(0xffffffffu, den, o);
    float aself = __expf(eself - m);
    den += aself;
    float invden = 1.f / den;

    float4 bv = ((const float4*)bias)[lane];
    float4 hv = *(const float4*)(h + (size_t)d * FEAT + lane * 4);
    float a0 = aself * invden;
    float4 acc;
    acc.x = fmaf(a0, hv.x, bv.x);
    acc.y = fmaf(a0, hv.y, bv.y);
    acc.z = fmaf(a0, hv.z, bv.z);
    acc.w = fmaf(a0, hv.w, bv.w);

#pragma unroll 2
    for (int j = beg; j < end; j++) {
        int s = g_csr_src[j];
        float e = g_ssrc[s] + sdst_d;
        e = e > 0.f ? e : 0.2f * e;
        float a = __expf(e - m) * invden;
        float4 v = *(const float4*)(h + (size_t)s * FEAT + lane * 4);
        acc.x = fmaf(a, v.x, acc.x);
        acc.y = fmaf(a, v.y, acc.y);
        acc.z = fmaf(a, v.z, acc.z);
        acc.w = fmaf(a, v.w, acc.w);
    }

    if (do_relu) {
        acc.x = fmaxf(acc.x, 0.f);
        acc.y = fmaxf(acc.y, 0.f);
        acc.z = fmaxf(acc.z, 0.f);
        acc.w = fmaxf(acc.w, 0.f);
    }
    *(float4*)(out + (size_t)d * FEAT + lane * 4) = acc;
}

// ---------------------------------------------------------------------------
// Final: y = h1 + h2; logits = y @ Wl + bl; log_softmax
// ---------------------------------------------------------------------------
__global__ void final_kernel(const float* __restrict__ h1, const float* __restrict__ h2,
                             const float* __restrict__ Wl, const float* __restrict__ bl,
                             float* __restrict__ out, int N) {
    __shared__ float Wls[FEAT * COUT];
    __shared__ float bls[COUT];
    __shared__ float ys[4][FEAT];
    __shared__ float red[4][2];

    int t = threadIdx.x;
    for (int i = t; i < FEAT * COUT; i += 256) Wls[i] = Wl[i];
    if (t < COUT) bls[t] = bl[t];
    int g = t >> 6;
    int c = t & 63;
    int wing = (t >> 5) & 1;

    for (int base = blockIdx.x * 4; base < N; base += gridDim.x * 4) {
        int node = base + g;
        bool act = node < N;
        __syncthreads();
        if (act) {
            const float* p1 = h1 + (size_t)node * FEAT;
            const float* p2 = h2 + (size_t)node * FEAT;
            ys[g][c]      = p1[c]      + p2[c];
            ys[g][c + 64] = p1[c + 64] + p2[c + 64];
        }
        __syncthreads();
        float acc = bls[c];
#pragma unroll 16
        for (int k = 0; k < FEAT; k++)
            acc = fmaf(ys[g][k], Wls[k * COUT + c], acc);

        float mx = acc;
#pragma unroll
        for (int o = 16; o; o >>= 1) mx = fmaxf(mx, __shfl_xor_sync(0xffffffffu, mx, o));
        if ((t & 31) == 0) red[g][wing] = mx;
        __syncthreads();
        mx = fmaxf(red[g][0], red[g][1]);
        __syncthreads();
        float sm = expf(acc - mx);
#pragma unroll
        for (int o = 16; o; o >>= 1) sm += __shfl_xor_sync(0xffffffffu, sm, o);
        if ((t & 31) == 0) red[g][wing] = sm;
        __syncthreads();
        sm = red[g][0] + red[g][1];
        if (act) out[(size_t)node * COUT + c] = acc - mx - logf(sm);
    }
}

__global__ void copy_edges_float(const void* ei, float* o, int n) {
    int i = blockIdx.x * blockDim.x + threadIdx.x;
    if (i >= n) return;
    long long v = g_is64 ? ((const long long*)ei)[i]
                         : (long long)((const int*)ei)[i];
    o[i] = (float)v;
}

// ---------------------------------------------------------------------------
// Host orchestration
// ---------------------------------------------------------------------------
extern "C" void kernel_launch(void* const* d_in, const int* in_sizes, int n_in,
                              void* d_out, int out_size) {
    const float* x   = (const float*)d_in[0];
    const void*  ei  = d_in[1];
    const float* W1  = (const float*)d_in[2];
    const float* a1s = (const float*)d_in[3];
    const float* a1d = (const float*)d_in[4];
    const float* b1  = (const float*)d_in[5];
    const float* W2  = (const float*)d_in[6];
    const float* a2s = (const float*)d_in[7];
    const float* a2d = (const float*)d_in[8];
    const float* b2  = (const float*)d_in[9];
    const float* Wl  = (const float*)d_in[10];
    const float* bl  = (const float*)d_in[11];

    int N = in_sizes[0] / FEAT;
    int E = in_sizes[1] / 2;

    float *h, *o1, *o2;
    cudaGetSymbolAddress((void**)&h,  g_h);
    cudaGetSymbolAddress((void**)&o1, g_o1);
    cudaGetSymbolAddress((void**)&o2, g_o2);

    // edge normalization + CSR build
    int ncheck = (2 * E < 2048) ? 2 * E : 2048;
    detect_kernel<<<1, 1>>>(ei, ncheck, N);
    deg_zero<<<(N + 255) / 256, 256>>>(N);
    convert_count<<<(2 * E + 255) / 256, 256>>>(ei, E);
    int nb = (N + SCAN_B - 1) / SCAN_B;
    scan_blocks<<<nb, SCAN_B>>>(N);
    scan_bsums<<<1, 32>>>(nb);
    add_offsets<<<(N + 255) / 256, 256>>>(N, E);
    csr_fill<<<(E + 255) / 256, 256>>>(E);

    int ggrid = (N + GBM - 1) / GBM;

    // layer 1: h1 = relu(gat(x))
    gemm_tf32<<<ggrid, 256>>>(x, W1, h, N);
    scores_kernel<<<(N + 7) / 8, 256>>>(h, a1s, a1d, N);
    node_gat<<<(N * 32 + 255) / 256, 256>>>(h, b1, o1, N, 1);

    // layer 2: h2 = gat(h1)
    gemm_tf32<<<ggrid, 256>>>(o1, W2, h, N);
    scores_kernel<<<(N + 7) / 8, 256>>>(h, a2s, a2d, N);
    node_gat<<<(N * 32 + 255) / 256, 256>>>(h, b2, o2, N, 0);

    // final: log_softmax((h1 + h2) @ Wl + bl)
    int fgrid = (N + 3) / 4;
    if (fgrid > 888) fgrid = 888;
    final_kernel<<<fgrid, 256>>>(o1, o2, Wl, bl, (float*)d_out, N);

    long long extra = (long long)out_size - (long long)N * COUT;
    if (extra == 2LL * E) {
        copy_edges_float<<<(2 * E + 255) / 256, 256>>>(ei, (float*)d_out + (size_t)N * COUT, 2 * E);
    } else if (extra == 4LL * E) {
        cudaMemcpyAsync((char*)d_out + (size_t)N * COUT * sizeof(float), ei,
                        sizeof(long long) * 2 * E, cudaMemcpyDeviceToDevice);
    }
}

// round 5
// speedup vs baseline: 4.0437x; 1.3261x over previous
#include <cuda_runtime.h>
#include <cuda_fp16.h>
#include <math.h>
#include <stdint.h>

#define MAXN   100000
#define MAXE   1600000
#define FEAT   128
#define COUT   64
#define LOWF   (-1e30f)

// ---------------------------------------------------------------------------
// Scratch (device globals — no allocations allowed)
// ---------------------------------------------------------------------------
__device__ float  g_h  [MAXN * FEAT];   // fp32 h (also reused for final logits)
__device__ __half g_h16[MAXN * FEAT];   // fp16 copy of h for gathers
__device__ float  g_o1 [MAXN * FEAT];
__device__ float  g_o2 [MAXN * FEAT];
__device__ float  g_ssrc[MAXN];
__device__ float  g_sdst[MAXN];
__device__ float  g_es  [MAXN];
__device__ float  g_ew  [MAXE];         // cached per-edge post-leaky logits
__device__ int    g_edges[2 * MAXE];
__device__ int    g_rowptr[MAXN + 1];
__device__ int    g_csr_src[MAXE];
__device__ int    g_deg [MAXN];
__device__ int    g_fill[MAXN];
__device__ int    g_boff[256];
__device__ int    g_is64;

// ---------------------------------------------------------------------------
// Edge dtype detection + normalization (+ fused degree count)
// ---------------------------------------------------------------------------
__global__ void detect_kernel(const void* ei, int n_check, int N) {
    if (threadIdx.x == 0 && blockIdx.x == 0) {
        const long long* p = (const long long*)ei;
        int is64 = 1;
        for (int i = 0; i < n_check; i++) {
            long long v = p[i];
            if (v < 0 || v >= (long long)N) { is64 = 0; break; }
        }
        g_is64 = is64;
    }
}

__global__ void convert_count(const void* ei, int E) {
    int i = blockIdx.x * blockDim.x + threadIdx.x;
    if (i >= 2 * E) return;
    int v;
    if (g_is64) v = (int)((const long long*)ei)[i];
    else        v = ((const int*)ei)[i];
    g_edges[i] = v;
    if (i >= E) atomicAdd(&g_deg[v], 1);
}

__global__ void deg_zero(int N) {
    int i = blockIdx.x * blockDim.x + threadIdx.x;
    if (i < N) { g_deg[i] = 0; g_fill[i] = 0; }
}

#define SCAN_B 1024
__global__ void scan_blocks(int N) {
    __shared__ int sh[SCAN_B];
    int tid = threadIdx.x;
    int i = blockIdx.x * SCAN_B + tid;
    int v = (i < N) ? g_deg[i] : 0;
    sh[tid] = v;
    __syncthreads();
#pragma unroll
    for (int o = 1; o < SCAN_B; o <<= 1) {
        int t = (tid >= o) ? sh[tid - o] : 0;
        __syncthreads();
        sh[tid] += t;
        __syncthreads();
    }
    if (i < N) g_rowptr[i] = sh[tid] - v;
    if (tid == SCAN_B - 1) g_boff[blockIdx.x] = sh[tid];
}

__global__ void scan_bsums(int nb) {
    if (threadIdx.x == 0 && blockIdx.x == 0) {
        int run = 0;
        for (int b = 0; b < nb; b++) { int v = g_boff[b]; g_boff[b] = run; run += v; }
    }
}

__global__ void add_offsets(int N, int E) {
    int i = blockIdx.x * blockDim.x + threadIdx.x;
    if (i < N) g_rowptr[i] += g_boff[i >> 10];
    if (i == 0) g_rowptr[N] = E;
}

__global__ void csr_fill(int E) {
    int i = blockIdx.x * blockDim.x + threadIdx.x;
    if (i >= E) return;
    int d = g_edges[E + i];
    int pos = g_rowptr[d] + atomicAdd(&g_fill[d], 1);
    g_csr_src[pos] = g_edges[i];
}

// ---------------------------------------------------------------------------
// tf32 GEMM helpers
// ---------------------------------------------------------------------------
__device__ __forceinline__ uint32_t f2tf32(float f) {
    uint32_t u;
    asm("cvt.rna.tf32.f32 %0, %1;" : "=r"(u) : "f"(f));
    return u;
}

__device__ __forceinline__ void mma_tf32(float4& c, const uint32_t a[4], const uint32_t b[2]) {
    asm volatile(
        "mma.sync.aligned.m16n8k8.row.col.f32.tf32.tf32.f32 "
        "{%0,%1,%2,%3}, {%4,%5,%6,%7}, {%8,%9}, {%0,%1,%2,%3};\n"
        : "+f"(c.x), "+f"(c.y), "+f"(c.z), "+f"(c.w)
        : "r"(a[0]), "r"(a[1]), "r"(a[2]), "r"(a[3]), "r"(b[0]), "r"(b[1]));
}

#define GBM 128
#define GBK 32
#define APAD 36
#define BPAD 132

// H[N,128] = A[N,128] @ W[128,128]; writes fp32 H and fp16 H16
__global__ void __launch_bounds__(256, 2)
gemm_tf32(const float* __restrict__ A, const float* __restrict__ W,
          float* __restrict__ H, __half* __restrict__ H16, int N) {
    __shared__ uint32_t As[GBM][APAD];
    __shared__ uint32_t Bs[GBK][BPAD];

    int t = threadIdx.x;
    int wid = t >> 5, lane = t & 31;
    int wm = wid >> 1, wn = wid & 1;
    int rowBase = blockIdx.x * GBM;
    int lg = lane >> 2;
    int lt = lane & 3;

    float4 c[2][8];
#pragma unroll
    for (int mt = 0; mt < 2; mt++)
#pragma unroll
        for (int nt = 0; nt < 8; nt++) c[mt][nt] = make_float4(0.f, 0.f, 0.f, 0.f);

    int arow = t >> 3;
    int acol = (t & 7) * 4;
    int brow = t >> 5;
    int bcol = lane * 4;

    for (int kk = 0; kk < FEAT; kk += GBK) {
#pragma unroll
        for (int v = 0; v < 4; v++) {
            int r = arow + v * 32;
            int gr = rowBase + r;
            float4 av = make_float4(0.f, 0.f, 0.f, 0.f);
            if (gr < N) av = *(const float4*)(A + (size_t)gr * FEAT + kk + acol);
            As[r][acol + 0] = f2tf32(av.x);
            As[r][acol + 1] = f2tf32(av.y);
            As[r][acol + 2] = f2tf32(av.z);
            As[r][acol + 3] = f2tf32(av.w);
        }
#pragma unroll
        for (int v = 0; v < 4; v++) {
            int r = brow + v * 8;
            float4 wv = *(const float4*)(W + (size_t)(kk + r) * FEAT + bcol);
            Bs[r][bcol + 0] = f2tf32(wv.x);
            Bs[r][bcol + 1] = f2tf32(wv.y);
            Bs[r][bcol + 2] = f2tf32(wv.z);
            Bs[r][bcol + 3] = f2tf32(wv.w);
        }
        __syncthreads();

#pragma unroll
        for (int ks = 0; ks < 4; ks++) {
            int k0 = ks * 8;
            uint32_t af[2][4];
#pragma unroll
            for (int mt = 0; mt < 2; mt++) {
                int row = wm * 32 + mt * 16 + lg;
                af[mt][0] = As[row][k0 + lt];
                af[mt][1] = As[row + 8][k0 + lt];
                af[mt][2] = As[row][k0 + lt + 4];
                af[mt][3] = As[row + 8][k0 + lt + 4];
            }
            uint32_t bf[8][2];
#pragma unroll
            for (int nt = 0; nt < 8; nt++) {
                int col = wn * 64 + nt * 8 + lg;
                bf[nt][0] = Bs[k0 + lt][col];
                bf[nt][1] = Bs[k0 + lt + 4][col];
            }
#pragma unroll
            for (int mt = 0; mt < 2; mt++)
#pragma unroll
                for (int nt = 0; nt < 8; nt++)
                    mma_tf32(c[mt][nt], af[mt], bf[nt]);
        }
        __syncthreads();
    }

#pragma unroll
    for (int mt = 0; mt < 2; mt++) {
        int row0 = rowBase + wm * 32 + mt * 16 + lg;
#pragma unroll
        for (int nt = 0; nt < 8; nt++) {
            int col = wn * 64 + nt * 8 + lt * 2;
            if (row0 < N) {
                *(float2*)(H + (size_t)row0 * FEAT + col) = make_float2(c[mt][nt].x, c[mt][nt].y);
                *(__half2*)(H16 + (size_t)row0 * FEAT + col) = __floats2half2_rn(c[mt][nt].x, c[mt][nt].y);
            }
            if (row0 + 8 < N) {
                *(float2*)(H + (size_t)(row0 + 8) * FEAT + col) = make_float2(c[mt][nt].z, c[mt][nt].w);
                *(__half2*)(H16 + (size_t)(row0 + 8) * FEAT + col) = __floats2half2_rn(c[mt][nt].z, c[mt][nt].w);
            }
        }
    }
}

// Final GEMM: L[N,64] = (A1+A2)[N,128] @ W[128,64] + bl
__global__ void __launch_bounds__(256, 2)
gemm_tf32_final(const float* __restrict__ A1, const float* __restrict__ A2,
                const float* __restrict__ W, const float* __restrict__ bl,
                float* __restrict__ L, int N) {
    __shared__ uint32_t As[GBM][APAD];
    __shared__ uint32_t Bs[GBK][68];

    int t = threadIdx.x;
    int wid = t >> 5, lane = t & 31;
    int wm = wid >> 1, wn = wid & 1;
    int rowBase = blockIdx.x * GBM;
    int lg = lane >> 2;
    int lt = lane & 3;

    float4 c[2][4];
#pragma unroll
    for (int mt = 0; mt < 2; mt++)
#pragma unroll
        for (int nt = 0; nt < 4; nt++) c[mt][nt] = make_float4(0.f, 0.f, 0.f, 0.f);

    int arow = t >> 3;
    int acol = (t & 7) * 4;

    for (int kk = 0; kk < FEAT; kk += GBK) {
#pragma unroll
        for (int v = 0; v < 4; v++) {
            int r = arow + v * 32;
            int gr = rowBase + r;
            float4 av = make_float4(0.f, 0.f, 0.f, 0.f);
            if (gr < N) {
                float4 a = *(const float4*)(A1 + (size_t)gr * FEAT + kk + acol);
                float4 b = *(const float4*)(A2 + (size_t)gr * FEAT + kk + acol);
                av = make_float4(a.x + b.x, a.y + b.y, a.z + b.z, a.w + b.w);
            }
            As[r][acol + 0] = f2tf32(av.x);
            As[r][acol + 1] = f2tf32(av.y);
            As[r][acol + 2] = f2tf32(av.z);
            As[r][acol + 3] = f2tf32(av.w);
        }
        // B: 32 x 64 = 512 float4 / 4 = ... 512 floats4? 32*64/4 = 512 float4 loads, 2 per thread
#pragma unroll
        for (int v = 0; v < 2; v++) {
            int idx = t + v * 256;
            int kr = idx >> 4;
            int nb = (idx & 15) * 4;
            float4 wv = *(const float4*)(W + (size_t)(kk + kr) * COUT + nb);
            Bs[kr][nb + 0] = f2tf32(wv.x);
            Bs[kr][nb + 1] = f2tf32(wv.y);
            Bs[kr][nb + 2] = f2tf32(wv.z);
            Bs[kr][nb + 3] = f2tf32(wv.w);
        }
        __syncthreads();

#pragma unroll
        for (int ks = 0; ks < 4; ks++) {
            int k0 = ks * 8;
            uint32_t af[2][4];
#pragma unroll
            for (int mt = 0; mt < 2; mt++) {
                int row = wm * 32 + mt * 16 + lg;
                af[mt][0] = As[row][k0 + lt];
                af[mt][1] = As[row + 8][k0 + lt];
                af[mt][2] = As[row][k0 + lt + 4];
                af[mt][3] = As[row + 8][k0 + lt + 4];
            }
            uint32_t bf[4][2];
#pragma unroll
            for (int nt = 0; nt < 4; nt++) {
                int col = wn * 32 + nt * 8 + lg;
                bf[nt][0] = Bs[k0 + lt][col];
                bf[nt][1] = Bs[k0 + lt + 4][col];
            }
#pragma unroll
            for (int mt = 0; mt < 2; mt++)
#pragma unroll
                for (int nt = 0; nt < 4; nt++)
                    mma_tf32(c[mt][nt], af[mt], bf[nt]);
        }
        __syncthreads();
    }

#pragma unroll
    for (int mt = 0; mt < 2; mt++) {
        int row0 = rowBase + wm * 32 + mt * 16 + lg;
#pragma unroll
        for (int nt = 0; nt < 4; nt++) {
            int col = wn * 32 + nt * 8 + lt * 2;
            float b0 = bl[col], b1 = bl[col + 1];
            if (row0 < N)
                *(float2*)(L + (size_t)row0 * COUT + col) = make_float2(c[mt][nt].x + b0, c[mt][nt].y + b1);
            if (row0 + 8 < N)
                *(float2*)(L + (size_t)(row0 + 8) * COUT + col) = make_float2(c[mt][nt].z + b0, c[mt][nt].w + b1);
        }
    }
}

// ---------------------------------------------------------------------------
// Per-node attention scores (warp per node)
// ---------------------------------------------------------------------------
__global__ void scores_kernel(const float* __restrict__ h,
                              const float* __restrict__ a_src,
                              const float* __restrict__ a_dst,
                              int N) {
    int warp = (blockIdx.x * blockDim.x + threadIdx.x) >> 5;
    int lane = threadIdx.x & 31;
    if (warp >= N) return;
    float4 hv = *(const float4*)(h + (size_t)warp * FEAT + lane * 4);
    float4 as = ((const float4*)a_src)[lane];
    float4 ad = ((const float4*)a_dst)[lane];
    float s1 = hv.x * as.x + hv.y * as.y + hv.z * as.z + hv.w * as.w;
    float s2 = hv.x * ad.x + hv.y * ad.y + hv.z * ad.z + hv.w * ad.w;
#pragma unroll
    for (int o = 16; o; o >>= 1) {
        s1 += __shfl_down_sync(0xffffffffu, s1, o);
        s2 += __shfl_down_sync(0xffffffffu, s2, o);
    }
    if (lane == 0) {
        g_ssrc[warp] = s1;
        g_sdst[warp] = s2;
        float e = s1 + s2;
        g_es[warp] = e > 0.f ? e : 0.2f * e;
    }
}

// ---------------------------------------------------------------------------
// Fused per-node GAT: online softmax over incoming edges + fp16 aggregation
// Warp per destination node.
// ---------------------------------------------------------------------------
__global__ void node_gat(const float* __restrict__ h, const __half* __restrict__ h16,
                         const float* __restrict__ bias,
                         float* __restrict__ out, int N, int do_relu) {
    int d = (blockIdx.x * blockDim.x + threadIdx.x) >> 5;
    int lane = threadIdx.x & 31;
    if (d >= N) return;

    int beg = g_rowptr[d];
    int end = g_rowptr[d + 1];
    float sdst_d = g_sdst[d];
    float eself = g_es[d];

    // pass A: online (max, denom) + cache edge logits
    float m = LOWF;
    float den = 0.f;
    for (int j = beg + lane; j < end; j += 32) {
        float e = g_ssrc[g_csr_src[j]] + sdst_d;
        e = e > 0.f ? e : 0.2f * e;
        g_ew[j] = e;
        if (e > m) { den = den * __expf(m - e) + 1.f; m = e; }
        else        den += __expf(e - m);
    }
#pragma unroll
    for (int o = 16; o; o >>= 1) {
        float mo = __shfl_xor_sync(0xffffffffu, m, o);
        float dn = __shfl_xor_sync(0xffffffffu, den, o);
        float M = fmaxf(m, mo);
        den = den * __expf(m - M) + dn * __expf(mo - M);
        m = M;
    }
    // fold self-loop
    {
        float M = fmaxf(m, eself);
        den = den * __expf(m - M) + __expf(eself - M);
        m = M;
    }
    float invden = 1.f / den;

    // pass B: aggregation (fp16 gathers, fp32 accum; self term fp32)
    float4 bv = ((const float4*)bias)[lane];
    float4 hv = *(const float4*)(h + (size_t)d * FEAT + lane * 4);
    float a0 = __expf(eself - m) * invden;
    float4 acc;
    acc.x = fmaf(a0, hv.x, bv.x);
    acc.y = fmaf(a0, hv.y, bv.y);
    acc.z = fmaf(a0, hv.z, bv.z);
    acc.w = fmaf(a0, hv.w, bv.w);

#pragma unroll 4
    for (int j = beg; j < end; j++) {
        int s = g_csr_src[j];
        float a = __expf(g_ew[j] - m) * invden;
        uint2 u = *(const uint2*)(h16 + (size_t)s * FEAT + lane * 4);
        float2 f0 = __half22float2(*(__half2*)&u.x);
        float2 f1 = __half22float2(*(__half2*)&u.y);
        acc.x = fmaf(a, f0.x, acc.x);
        acc.y = fmaf(a, f0.y, acc.y);
        acc.z = fmaf(a, f1.x, acc.z);
        acc.w = fmaf(a, f1.y, acc.w);
    }

    if (do_relu) {
        acc.x = fmaxf(acc.x, 0.f);
        acc.y = fmaxf(acc.y, 0.f);
        acc.z = fmaxf(acc.z, 0.f);
        acc.w = fmaxf(acc.w, 0.f);
    }
    *(float4*)(out + (size_t)d * FEAT + lane * 4) = acc;
}

// ---------------------------------------------------------------------------
// Row log-softmax over logits [N, 64] (warp per row)
// ---------------------------------------------------------------------------
__global__ void logsoftmax_kernel(const float* __restrict__ L, float* __restrict__ out, int N) {
    int row = (blockIdx.x * blockDim.x + threadIdx.x) >> 5;
    int lane = threadIdx.x & 31;
    if (row >= N) return;
    float v0 = L[(size_t)row * COUT + lane];
    float v1 = L[(size_t)row * COUT + lane + 32];
    float m = fmaxf(v0, v1);
#pragma unroll
    for (int o = 16; o; o >>= 1) m = fmaxf(m, __shfl_xor_sync(0xffffffffu, m, o));
    float s = expf(v0 - m) + expf(v1 - m);
#pragma unroll
    for (int o = 16; o; o >>= 1) s += __shfl_xor_sync(0xffffffffu, s, o);
    float ls = m + logf(s);
    out[(size_t)row * COUT + lane]      = v0 - ls;
    out[(size_t)row * COUT + lane + 32] = v1 - ls;
}

__global__ void copy_edges_float(const void* ei, float* o, int n) {
    int i = blockIdx.x * blockDim.x + threadIdx.x;
    if (i >= n) return;
    long long v = g_is64 ? ((const long long*)ei)[i]
                         : (long long)((const int*)ei)[i];
    o[i] = (float)v;
}

// ---------------------------------------------------------------------------
// Host orchestration
// ---------------------------------------------------------------------------
extern "C" void kernel_launch(void* const* d_in, const int* in_sizes, int n_in,
                              void* d_out, int out_size) {
    const float* x   = (const float*)d_in[0];
    const void*  ei  = d_in[1];
    const float* W1  = (const float*)d_in[2];
    const float* a1s = (const float*)d_in[3];
    const float* a1d = (const float*)d_in[4];
    const float* b1  = (const float*)d_in[5];
    const float* W2  = (const float*)d_in[6];
    const float* a2s = (const float*)d_in[7];
    const float* a2d = (const float*)d_in[8];
    const float* b2  = (const float*)d_in[9];
    const float* Wl  = (const float*)d_in[10];
    const float* bl  = (const float*)d_in[11];

    int N = in_sizes[0] / FEAT;
    int E = in_sizes[1] / 2;

    float *h, *o1, *o2;
    __half* h16;
    cudaGetSymbolAddress((void**)&h,   g_h);
    cudaGetSymbolAddress((void**)&h16, g_h16);
    cudaGetSymbolAddress((void**)&o1,  g_o1);
    cudaGetSymbolAddress((void**)&o2,  g_o2);

    // edge normalization + CSR build
    int ncheck = (2 * E < 2048) ? 2 * E : 2048;
    detect_kernel<<<1, 1>>>(ei, ncheck, N);
    deg_zero<<<(N + 255) / 256, 256>>>(N);
    convert_count<<<(2 * E + 255) / 256, 256>>>(ei, E);
    int nb = (N + SCAN_B - 1) / SCAN_B;
    scan_blocks<<<nb, SCAN_B>>>(N);
    scan_bsums<<<1, 32>>>(nb);
    add_offsets<<<(N + 255) / 256, 256>>>(N, E);
    csr_fill<<<(E + 255) / 256, 256>>>(E);

    int ggrid = (N + GBM - 1) / GBM;

    // layer 1: o1 = relu(gat(x))
    gemm_tf32<<<ggrid, 256>>>(x, W1, h, h16, N);
    scores_kernel<<<(N + 7) / 8, 256>>>(h, a1s, a1d, N);
    node_gat<<<(N * 32 + 255) / 256, 256>>>(h, h16, b1, o1, N, 1);

    // layer 2: o2 = gat(o1)
    gemm_tf32<<<ggrid, 256>>>(o1, W2, h, h16, N);
    scores_kernel<<<(N + 7) / 8, 256>>>(h, a2s, a2d, N);
    node_gat<<<(N * 32 + 255) / 256, 256>>>(h, h16, b2, o2, N, 0);

    // final: log_softmax((o1 + o2) @ Wl + bl) — logits into reused g_h scratch
    gemm_tf32_final<<<ggrid, 256>>>(o1, o2, Wl, bl, h, N);
    logsoftmax_kernel<<<(N * 32 + 255) / 256, 256>>>(h, (float*)d_out, N);

    long long extra = (long long)out_size - (long long)N * COUT;
    if (extra == 2LL * E) {
        copy_edges_float<<<(2 * E + 255) / 256, 256>>>(ei, (float*)d_out + (size_t)N * COUT, 2 * E);
    } else if (extra == 4LL * E) {
        cudaMemcpyAsync((char*)d_out + (size_t)N * COUT * sizeof(float), ei,
                        sizeof(long long) * 2 * E, cudaMemcpyDeviceToDevice);
    }
}

// round 6
// speedup vs baseline: 4.5508x; 1.1254x over previous
#include <cuda_runtime.h>
#include <cuda_fp16.h>
#include <math.h>
#include <stdint.h>

#define MAXN   100000
#define MAXE   1600000
#define FEAT   128
#define COUT   64
#define LOWF   (-1e30f)

// ---------------------------------------------------------------------------
// Scratch (device globals — no allocations allowed)
// ---------------------------------------------------------------------------
__device__ float  g_h  [MAXN * FEAT];   // logits scratch for the final layer
__device__ __half g_h16[MAXN * FEAT];   // fp16 h (gather + self + scores source)
__device__ float  g_o1 [MAXN * FEAT];
__device__ float  g_o2 [MAXN * FEAT];
__device__ float  g_ssrc[MAXN];
__device__ float  g_sdst[MAXN];
__device__ float  g_es  [MAXN];
__device__ float  g_ew  [MAXE];         // cached per-edge post-leaky logits
__device__ int    g_edges[2 * MAXE];
__device__ int    g_rowptr[MAXN + 1];
__device__ int    g_csr_src[MAXE];
__device__ int    g_deg [MAXN];
__device__ int    g_fill[MAXN];
__device__ int    g_boff[256];
__device__ int    g_is64;

// ---------------------------------------------------------------------------
// Edge dtype detection (parallel) + normalization (+ fused degree count)
// ---------------------------------------------------------------------------
__global__ void detect_kernel(const void* ei, int n_check, int N) {
    const long long* p = (const long long*)ei;
    int ok = 1;
    for (int i = threadIdx.x; i < n_check; i += blockDim.x) {
        long long v = p[i];
        if (v < 0 || v >= (long long)N) ok = 0;
    }
    int all = __syncthreads_and(ok);
    if (threadIdx.x == 0) g_is64 = all;
}

__global__ void convert_count(const void* ei, int E) {
    int i = blockIdx.x * blockDim.x + threadIdx.x;
    if (i >= 2 * E) return;
    int v;
    if (g_is64) v = (int)((const long long*)ei)[i];
    else        v = ((const int*)ei)[i];
    g_edges[i] = v;
    if (i >= E) atomicAdd(&g_deg[v], 1);
}

#define SCAN_B 1024
__global__ void scan_blocks(int N) {
    __shared__ int sh[SCAN_B];
    int tid = threadIdx.x;
    int i = blockIdx.x * SCAN_B + tid;
    int v = (i < N) ? g_deg[i] : 0;
    sh[tid] = v;
    __syncthreads();
#pragma unroll
    for (int o = 1; o < SCAN_B; o <<= 1) {
        int t = (tid >= o) ? sh[tid - o] : 0;
        __syncthreads();
        sh[tid] += t;
        __syncthreads();
    }
    if (i < N) g_rowptr[i] = sh[tid] - v;
    if (tid == SCAN_B - 1) g_boff[blockIdx.x] = sh[tid];
}

__global__ void scan_bsums(int nb) {
    if (threadIdx.x == 0 && blockIdx.x == 0) {
        int run = 0;
        for (int b = 0; b < nb; b++) { int v = g_boff[b]; g_boff[b] = run; run += v; }
    }
}

__global__ void add_offsets(int N, int E) {
    int i = blockIdx.x * blockDim.x + threadIdx.x;
    if (i < N) g_rowptr[i] += g_boff[i >> 10];
    if (i == 0) g_rowptr[N] = E;
}

__global__ void csr_fill(int E) {
    int i = blockIdx.x * blockDim.x + threadIdx.x;
    if (i >= E) return;
    int d = g_edges[E + i];
    int pos = g_rowptr[d] + atomicAdd(&g_fill[d], 1);
    g_csr_src[pos] = g_edges[i];
}

// ---------------------------------------------------------------------------
// tf32 GEMM helpers
// ---------------------------------------------------------------------------
__device__ __forceinline__ uint32_t f2tf32(float f) {
    uint32_t u;
    asm("cvt.rna.tf32.f32 %0, %1;" : "=r"(u) : "f"(f));
    return u;
}

__device__ __forceinline__ void mma_tf32(float4& c, const uint32_t a[4], const uint32_t b[2]) {
    asm volatile(
        "mma.sync.aligned.m16n8k8.row.col.f32.tf32.tf32.f32 "
        "{%0,%1,%2,%3}, {%4,%5,%6,%7}, {%8,%9}, {%0,%1,%2,%3};\n"
        : "+f"(c.x), "+f"(c.y), "+f"(c.z), "+f"(c.w)
        : "r"(a[0]), "r"(a[1]), "r"(a[2]), "r"(a[3]), "r"(b[0]), "r"(b[1]));
}

#define GBM 128
#define GBK 32
#define APAD 36
#define BPAD 132

// h16[N,128] = fp16(A[N,128] @ W[128,128]); fused per-row attention scores
// s_src/s_dst from fp32 accumulators.
__global__ void __launch_bounds__(256, 2)
gemm_tf32(const float* __restrict__ A, const float* __restrict__ W,
          const float* __restrict__ a_src, const float* __restrict__ a_dst,
          __half* __restrict__ H16, int N) {
    __shared__ uint32_t As[GBM][APAD];
    __shared__ uint32_t Bs[GBK][BPAD];
    __shared__ float sAs[FEAT], sAd[FEAT];
    __shared__ float redS[GBM][2], redD[GBM][2];

    int t = threadIdx.x;
    int wid = t >> 5, lane = t & 31;
    int wm = wid >> 1, wn = wid & 1;
    int rowBase = blockIdx.x * GBM;
    int lg = lane >> 2;
    int lt = lane & 3;

    if (t < FEAT) { sAs[t] = a_src[t]; sAd[t] = a_dst[t]; }

    float4 c[2][8];
#pragma unroll
    for (int mt = 0; mt < 2; mt++)
#pragma unroll
        for (int nt = 0; nt < 8; nt++) c[mt][nt] = make_float4(0.f, 0.f, 0.f, 0.f);

    int arow = t >> 3;
    int acol = (t & 7) * 4;
    int brow = t >> 5;
    int bcol = lane * 4;

    for (int kk = 0; kk < FEAT; kk += GBK) {
#pragma unroll
        for (int v = 0; v < 4; v++) {
            int r = arow + v * 32;
            int gr = rowBase + r;
            float4 av = make_float4(0.f, 0.f, 0.f, 0.f);
            if (gr < N) av = *(const float4*)(A + (size_t)gr * FEAT + kk + acol);
            As[r][acol + 0] = f2tf32(av.x);
            As[r][acol + 1] = f2tf32(av.y);
            As[r][acol + 2] = f2tf32(av.z);
            As[r][acol + 3] = f2tf32(av.w);
        }
#pragma unroll
        for (int v = 0; v < 4; v++) {
            int r = brow + v * 8;
            float4 wv = *(const float4*)(W + (size_t)(kk + r) * FEAT + bcol);
            Bs[r][bcol + 0] = f2tf32(wv.x);
            Bs[r][bcol + 1] = f2tf32(wv.y);
            Bs[r][bcol + 2] = f2tf32(wv.z);
            Bs[r][bcol + 3] = f2tf32(wv.w);
        }
        __syncthreads();

#pragma unroll
        for (int ks = 0; ks < 4; ks++) {
            int k0 = ks * 8;
            uint32_t af[2][4];
#pragma unroll
            for (int mt = 0; mt < 2; mt++) {
                int row = wm * 32 + mt * 16 + lg;
                af[mt][0] = As[row][k0 + lt];
                af[mt][1] = As[row + 8][k0 + lt];
                af[mt][2] = As[row][k0 + lt + 4];
                af[mt][3] = As[row + 8][k0 + lt + 4];
            }
            uint32_t bf[8][2];
#pragma unroll
            for (int nt = 0; nt < 8; nt++) {
                int col = wn * 64 + nt * 8 + lg;
                bf[nt][0] = Bs[k0 + lt][col];
                bf[nt][1] = Bs[k0 + lt + 4][col];
            }
#pragma unroll
            for (int mt = 0; mt < 2; mt++)
#pragma unroll
                for (int nt = 0; nt < 8; nt++)
                    mma_tf32(c[mt][nt], af[mt], bf[nt]);
        }
        __syncthreads();
    }

    // epilogue: fp16 store + fused score partials
#pragma unroll
    for (int mt = 0; mt < 2; mt++) {
        int rl0 = wm * 32 + mt * 16 + lg;          // local row
        int row0 = rowBase + rl0;
        float pS0 = 0.f, pS8 = 0.f, pD0 = 0.f, pD8 = 0.f;
#pragma unroll
        for (int nt = 0; nt < 8; nt++) {
            int col = wn * 64 + nt * 8 + lt * 2;
            float as0 = sAs[col], as1 = sAs[col + 1];
            float ad0 = sAd[col], ad1 = sAd[col + 1];
            pS0 += c[mt][nt].x * as0 + c[mt][nt].y * as1;
            pD0 += c[mt][nt].x * ad0 + c[mt][nt].y * ad1;
            pS8 += c[mt][nt].z * as0 + c[mt][nt].w * as1;
            pD8 += c[mt][nt].z * ad0 + c[mt][nt].w * ad1;
            if (row0 < N)
                *(__half2*)(H16 + (size_t)row0 * FEAT + col) = __floats2half2_rn(c[mt][nt].x, c[mt][nt].y);
            if (row0 + 8 < N)
                *(__half2*)(H16 + (size_t)(row0 + 8) * FEAT + col) = __floats2half2_rn(c[mt][nt].z, c[mt][nt].w);
        }
        // reduce over the 4-lane lt group
#pragma unroll
        for (int o = 1; o < 4; o <<= 1) {
            pS0 += __shfl_xor_sync(0xffffffffu, pS0, o);
            pS8 += __shfl_xor_sync(0xffffffffu, pS8, o);
            pD0 += __shfl_xor_sync(0xffffffffu, pD0, o);
            pD8 += __shfl_xor_sync(0xffffffffu, pD8, o);
        }
        if (lt == 0) {
            redS[rl0][wn] = pS0;  redD[rl0][wn] = pD0;
            redS[rl0 + 8][wn] = pS8;  redD[rl0 + 8][wn] = pD8;
        }
    }
    __syncthreads();
    if (t < GBM) {
        int grow = rowBase + t;
        if (grow < N) {
            float s1 = redS[t][0] + redS[t][1];
            float s2 = redD[t][0] + redD[t][1];
            g_ssrc[grow] = s1;
            g_sdst[grow] = s2;
            float e = s1 + s2;
            g_es[grow] = e > 0.f ? e : 0.2f * e;
        }
    }
}

// Final GEMM: L[N,64] = (A1+A2)[N,128] @ W[128,64] + bl
__global__ void __launch_bounds__(256, 2)
gemm_tf32_final(const float* __restrict__ A1, const float* __restrict__ A2,
                const float* __restrict__ W, const float* __restrict__ bl,
                float* __restrict__ L, int N) {
    __shared__ uint32_t As[GBM][APAD];
    __shared__ uint32_t Bs[GBK][68];

    int t = threadIdx.x;
    int wid = t >> 5, lane = t & 31;
    int wm = wid >> 1, wn = wid & 1;
    int rowBase = blockIdx.x * GBM;
    int lg = lane >> 2;
    int lt = lane & 3;

    float4 c[2][4];
#pragma unroll
    for (int mt = 0; mt < 2; mt++)
#pragma unroll
        for (int nt = 0; nt < 4; nt++) c[mt][nt] = make_float4(0.f, 0.f, 0.f, 0.f);

    int arow = t >> 3;
    int acol = (t & 7) * 4;

    for (int kk = 0; kk < FEAT; kk += GBK) {
#pragma unroll
        for (int v = 0; v < 4; v++) {
            int r = arow + v * 32;
            int gr = rowBase + r;
            float4 av = make_float4(0.f, 0.f, 0.f, 0.f);
            if (gr < N) {
                float4 a = *(const float4*)(A1 + (size_t)gr * FEAT + kk + acol);
                float4 b = *(const float4*)(A2 + (size_t)gr * FEAT + kk + acol);
                av = make_float4(a.x + b.x, a.y + b.y, a.z + b.z, a.w + b.w);
            }
            As[r][acol + 0] = f2tf32(av.x);
            As[r][acol + 1] = f2tf32(av.y);
            As[r][acol + 2] = f2tf32(av.z);
            As[r][acol + 3] = f2tf32(av.w);
        }
#pragma unroll
        for (int v = 0; v < 2; v++) {
            int idx = t + v * 256;
            int kr = idx >> 4;
            int nb = (idx & 15) * 4;
            float4 wv = *(const float4*)(W + (size_t)(kk + kr) * COUT + nb);
            Bs[kr][nb + 0] = f2tf32(wv.x);
            Bs[kr][nb + 1] = f2tf32(wv.y);
            Bs[kr][nb + 2] = f2tf32(wv.z);
            Bs[kr][nb + 3] = f2tf32(wv.w);
        }
        __syncthreads();

#pragma unroll
        for (int ks = 0; ks < 4; ks++) {
            int k0 = ks * 8;
            uint32_t af[2][4];
#pragma unroll
            for (int mt = 0; mt < 2; mt++) {
                int row = wm * 32 + mt * 16 + lg;
                af[mt][0] = As[row][k0 + lt];
                af[mt][1] = As[row + 8][k0 + lt];
                af[mt][2] = As[row][k0 + lt + 4];
                af[mt][3] = As[row + 8][k0 + lt + 4];
            }
            uint32_t bf[4][2];
#pragma unroll
            for (int nt = 0; nt < 4; nt++) {
                int col = wn * 32 + nt * 8 + lg;
                bf[nt][0] = Bs[k0 + lt][col];
                bf[nt][1] = Bs[k0 + lt + 4][col];
            }
#pragma unroll
            for (int mt = 0; mt < 2; mt++)
#pragma unroll
                for (int nt = 0; nt < 4; nt++)
                    mma_tf32(c[mt][nt], af[mt], bf[nt]);
        }
        __syncthreads();
    }

#pragma unroll
    for (int mt = 0; mt < 2; mt++) {
        int row0 = rowBase + wm * 32 + mt * 16 + lg;
#pragma unroll
        for (int nt = 0; nt < 4; nt++) {
            int col = wn * 32 + nt * 8 + lt * 2;
            float b0 = bl[col], b1 = bl[col + 1];
            if (row0 < N)
                *(float2*)(L + (size_t)row0 * COUT + col) = make_float2(c[mt][nt].x + b0, c[mt][nt].y + b1);
            if (row0 + 8 < N)
                *(float2*)(L + (size_t)(row0 + 8) * COUT + col) = make_float2(c[mt][nt].z + b0, c[mt][nt].w + b1);
        }
    }
}

// ---------------------------------------------------------------------------
// Fused per-node GAT: online softmax + fp16 aggregation. Warp per node.
// ---------------------------------------------------------------------------
__global__ void node_gat(const __half* __restrict__ h16,
                         const float* __restrict__ bias,
                         float* __restrict__ out, int N, int do_relu) {
    int d = (blockIdx.x * blockDim.x + threadIdx.x) >> 5;
    int lane = threadIdx.x & 31;
    if (d >= N) return;

    int beg = g_rowptr[d];
    int end = g_rowptr[d + 1];
    float sdst_d = g_sdst[d];
    float eself = g_es[d];

    // pass A: online (max, denom) + cache edge logits
    float m = LOWF;
    float den = 0.f;
    for (int j = beg + lane; j < end; j += 32) {
        float e = g_ssrc[g_csr_src[j]] + sdst_d;
        e = e > 0.f ? e : 0.2f * e;
        g_ew[j] = e;
        if (e > m) { den = den * __expf(m - e) + 1.f; m = e; }
        else        den += __expf(e - m);
    }
#pragma unroll
    for (int o = 16; o; o >>= 1) {
        float mo = __shfl_xor_sync(0xffffffffu, m, o);
        float dn = __shfl_xor_sync(0xffffffffu, den, o);
        float M = fmaxf(m, mo);
        den = den * __expf(m - M) + dn * __expf(mo - M);
        m = M;
    }
    {
        float M = fmaxf(m, eself);
        den = den * __expf(m - M) + __expf(eself - M);
        m = M;
    }
    float invden = 1.f / den;

    // pass B: aggregation (fp16 gathers, fp32 accum)
    float4 bv = ((const float4*)bias)[lane];
    uint2 us = *(const uint2*)(h16 + (size_t)d * FEAT + lane * 4);
    float2 s0 = __half22float2(*(__half2*)&us.x);
    float2 s1 = __half22float2(*(__half2*)&us.y);
    float a0 = __expf(eself - m) * invden;
    float4 acc;
    acc.x = fmaf(a0, s0.x, bv.x);
    acc.y = fmaf(a0, s0.y, bv.y);
    acc.z = fmaf(a0, s1.x, bv.z);
    acc.w = fmaf(a0, s1.y, bv.w);

#pragma unroll 4
    for (int j = beg; j < end; j++) {
        int s = g_csr_src[j];
        float a = __expf(g_ew[j] - m) * invden;
        uint2 u = *(const uint2*)(h16 + (size_t)s * FEAT + lane * 4);
        float2 f0 = __half22float2(*(__half2*)&u.x);
        float2 f1 = __half22float2(*(__half2*)&u.y);
        acc.x = fmaf(a, f0.x, acc.x);
        acc.y = fmaf(a, f0.y, acc.y);
        acc.z = fmaf(a, f1.x, acc.z);
        acc.w = fmaf(a, f1.y, acc.w);
    }

    if (do_relu) {
        acc.x = fmaxf(acc.x, 0.f);
        acc.y = fmaxf(acc.y, 0.f);
        acc.z = fmaxf(acc.z, 0.f);
        acc.w = fmaxf(acc.w, 0.f);
    }
    *(float4*)(out + (size_t)d * FEAT + lane * 4) = acc;
}

// ---------------------------------------------------------------------------
// Row log-softmax over logits [N, 64] (warp per row)
// ---------------------------------------------------------------------------
__global__ void logsoftmax_kernel(const float* __restrict__ L, float* __restrict__ out, int N) {
    int row = (blockIdx.x * blockDim.x + threadIdx.x) >> 5;
    int lane = threadIdx.x & 31;
    if (row >= N) return;
    float v0 = L[(size_t)row * COUT + lane];
    float v1 = L[(size_t)row * COUT + lane + 32];
    float m = fmaxf(v0, v1);
#pragma unroll
    for (int o = 16; o; o >>= 1) m = fmaxf(m, __shfl_xor_sync(0xffffffffu, m, o));
    float s = expf(v0 - m) + expf(v1 - m);
#pragma unroll
    for (int o = 16; o; o >>= 1) s += __shfl_xor_sync(0xffffffffu, s, o);
    float ls = m + logf(s);
    out[(size_t)row * COUT + lane]      = v0 - ls;
    out[(size_t)row * COUT + lane + 32] = v1 - ls;
}

__global__ void copy_edges_float(const void* ei, float* o, int n) {
    int i = blockIdx.x * blockDim.x + threadIdx.x;
    if (i >= n) return;
    long long v = g_is64 ? ((const long long*)ei)[i]
                         : (long long)((const int*)ei)[i];
    o[i] = (float)v;
}

// ---------------------------------------------------------------------------
// Host orchestration
// ---------------------------------------------------------------------------
extern "C" void kernel_launch(void* const* d_in, const int* in_sizes, int n_in,
                              void* d_out, int out_size) {
    const float* x   = (const float*)d_in[0];
    const void*  ei  = d_in[1];
    const float* W1  = (const float*)d_in[2];
    const float* a1s = (const float*)d_in[3];
    const float* a1d = (const float*)d_in[4];
    const float* b1  = (const float*)d_in[5];
    const float* W2  = (const float*)d_in[6];
    const float* a2s = (const float*)d_in[7];
    const float* a2d = (const float*)d_in[8];
    const float* b2  = (const float*)d_in[9];
    const float* Wl  = (const float*)d_in[10];
    const float* bl  = (const float*)d_in[11];

    int N = in_sizes[0] / FEAT;
    int E = in_sizes[1] / 2;

    float *h, *o1, *o2;
    __half* h16;
    void* pdeg; void* pfill;
    cudaGetSymbolAddress((void**)&h,   g_h);
    cudaGetSymbolAddress((void**)&h16, g_h16);
    cudaGetSymbolAddress((void**)&o1,  g_o1);
    cudaGetSymbolAddress((void**)&o2,  g_o2);
    cudaGetSymbolAddress(&pdeg,  g_deg);
    cudaGetSymbolAddress(&pfill, g_fill);

    // edge normalization + CSR build
    int ncheck = (2 * E < 2048) ? 2 * E : 2048;
    detect_kernel<<<1, 1024>>>(ei, ncheck, N);
    cudaMemsetAsync(pdeg,  0, (size_t)N * sizeof(int));
    cudaMemsetAsync(pfill, 0, (size_t)N * sizeof(int));
    convert_count<<<(2 * E + 255) / 256, 256>>>(ei, E);
    int nb = (N + SCAN_B - 1) / SCAN_B;
    scan_blocks<<<nb, SCAN_B>>>(N);
    scan_bsums<<<1, 32>>>(nb);
    add_offsets<<<(N + 255) / 256, 256>>>(N, E);
    csr_fill<<<(E + 255) / 256, 256>>>(E);

    int ggrid = (N + GBM - 1) / GBM;

    // layer 1: o1 = relu(gat(x))
    gemm_tf32<<<ggrid, 256>>>(x, W1, a1s, a1d, h16, N);
    node_gat<<<(N * 32 + 255) / 256, 256>>>(h16, b1, o1, N, 1);

    // layer 2: o2 = gat(o1)
    gemm_tf32<<<ggrid, 256>>>(o1, W2, a2s, a2d, h16, N);
    node_gat<<<(N * 32 + 255) / 256, 256>>>(h16, b2, o2, N, 0);

    // final: log_softmax((o1 + o2) @ Wl + bl)
    gemm_tf32_final<<<ggrid, 256>>>(o1, o2, Wl, bl, h, N);
    logsoftmax_kernel<<<(N * 32 + 255) / 256, 256>>>(h, (float*)d_out, N);

    long long extra = (long long)out_size - (long long)N * COUT;
    if (extra == 2LL * E) {
        copy_edges_float<<<(2 * E + 255) / 256, 256>>>(ei, (float*)d_out + (size_t)N * COUT, 2 * E);
    } else if (extra == 4LL * E) {
        cudaMemcpyAsync((char*)d_out + (size_t)N * COUT * sizeof(float), ei,
                        sizeof(long long) * 2 * E, cudaMemcpyDeviceToDevice);
    }
}

// round 7
// speedup vs baseline: 5.0119x; 1.1013x over previous
#include <cuda_runtime.h>
#include <cuda_fp16.h>
#include <math.h>
#include <stdint.h>

#define MAXN   100000
#define MAXE   1600000
#define FEAT   128
#define COUT   64
#define LOWF   (-1e30f)

// ---------------------------------------------------------------------------
// Scratch (device globals — no allocations allowed)
// ---------------------------------------------------------------------------
__device__ float  g_h  [MAXN * FEAT];   // logits scratch for the final layer
__device__ __half g_h16[MAXN * FEAT];   // fp16 h (gather + self source)
__device__ float  g_o1 [MAXN * FEAT];
__device__ float  g_o2 [MAXN * FEAT];
__device__ float  g_ssrc[MAXN];
__device__ float  g_sdst[MAXN];
__device__ float  g_es  [MAXN];
__device__ float  g_ew  [MAXE];         // cached per-edge post-leaky logits
__device__ int    g_edges[2 * MAXE];
__device__ int    g_rowptr[MAXN + 1];
__device__ int    g_csr_src[MAXE];
__device__ int    g_deg [MAXN];
__device__ int    g_fill[MAXN];
__device__ int    g_boff[256];
__device__ int    g_is64;

// ---------------------------------------------------------------------------
// Edge dtype detection (parallel) + normalization (+ fused degree count)
// ---------------------------------------------------------------------------
__global__ void detect_kernel(const void* ei, int n_check, int N) {
    const long long* p = (const long long*)ei;
    int ok = 1;
    for (int i = threadIdx.x; i < n_check; i += blockDim.x) {
        long long v = p[i];
        if (v < 0 || v >= (long long)N) ok = 0;
    }
    int all = __syncthreads_and(ok);
    if (threadIdx.x == 0) g_is64 = all;
}

__global__ void convert_count(const void* ei, int E) {
    int i = blockIdx.x * blockDim.x + threadIdx.x;
    if (i >= 2 * E) return;
    int v;
    if (g_is64) v = (int)((const long long*)ei)[i];
    else        v = ((const int*)ei)[i];
    g_edges[i] = v;
    if (i >= E) atomicAdd(&g_deg[v], 1);
}

#define SCAN_B 1024
__global__ void scan_blocks(int N) {
    __shared__ int sh[SCAN_B];
    int tid = threadIdx.x;
    int i = blockIdx.x * SCAN_B + tid;
    int v = (i < N) ? g_deg[i] : 0;
    sh[tid] = v;
    __syncthreads();
#pragma unroll
    for (int o = 1; o < SCAN_B; o <<= 1) {
        int t = (tid >= o) ? sh[tid - o] : 0;
        __syncthreads();
        sh[tid] += t;
        __syncthreads();
    }
    if (i < N) g_rowptr[i] = sh[tid] - v;
    if (tid == SCAN_B - 1) g_boff[blockIdx.x] = sh[tid];
}

// parallel exclusive scan of per-block sums (nb <= 256)
__global__ void scan_bsums(int nb) {
    __shared__ int sh[256];
    int t = threadIdx.x;
    int v = (t < nb) ? g_boff[t] : 0;
    sh[t] = v;
    __syncthreads();
#pragma unroll
    for (int o = 1; o < 256; o <<= 1) {
        int x = (t >= o) ? sh[t - o] : 0;
        __syncthreads();
        sh[t] += x;
        __syncthreads();
    }
    if (t < nb) g_boff[t] = sh[t] - v;
}

__global__ void add_offsets(int N, int E) {
    int i = blockIdx.x * blockDim.x + threadIdx.x;
    if (i < N) g_rowptr[i] += g_boff[i >> 10];
    if (i == 0) g_rowptr[N] = E;
}

__global__ void csr_fill(int E) {
    int i = blockIdx.x * blockDim.x + threadIdx.x;
    if (i >= E) return;
    int d = g_edges[E + i];
    int pos = g_rowptr[d] + atomicAdd(&g_fill[d], 1);
    g_csr_src[pos] = g_edges[i];
}

// ---------------------------------------------------------------------------
// fp16 HMMA GEMM helpers
// ---------------------------------------------------------------------------
__device__ __forceinline__ uint32_t pack_half2(float a, float b) {
    __half2 h = __floats2half2_rn(a, b);
    return *reinterpret_cast<uint32_t*>(&h);
}

__device__ __forceinline__ void mma_f16(float4& c, const uint32_t a[4], const uint32_t b[2]) {
    asm volatile(
        "mma.sync.aligned.m16n8k16.row.col.f32.f16.f16.f32 "
        "{%0,%1,%2,%3}, {%4,%5,%6,%7}, {%8,%9}, {%0,%1,%2,%3};\n"
        : "+f"(c.x), "+f"(c.y), "+f"(c.z), "+f"(c.w)
        : "r"(a[0]), "r"(a[1]), "r"(a[2]), "r"(a[3]), "r"(b[0]), "r"(b[1]));
}

#define GBM 128
#define GBK 32
#define ASTR 20     // uint32 (half2) per A row: 16 data + 4 pad  -> conflict-free frags
#define BSTR 136    // uint32 per B k-pair row: 128 data + 8 pad  -> conflict-free frags
#define BSTRF 72    // final GEMM: 64 data + 8 pad

// h16[N,128] = fp16(A[N,128] @ W[128,128]); fused per-row attention scores.
// A,W converted to fp16 at SMEM-store time (same 10-bit mantissa as tf32).
__global__ void __launch_bounds__(256, 2)
gemm_f16(const float* __restrict__ A, const float* __restrict__ W,
         const float* __restrict__ a_src, const float* __restrict__ a_dst,
         __half* __restrict__ H16, int N) {
    __shared__ uint32_t As[GBM][ASTR];       // [row][k-pair]
    __shared__ uint32_t Bs[GBK / 2][BSTR];   // [k-pair][col]
    __shared__ float sAs[FEAT], sAd[FEAT];
    __shared__ float redS[GBM][2], redD[GBM][2];

    int t = threadIdx.x;
    int wid = t >> 5, lane = t & 31;
    int wm = wid >> 1, wn = wid & 1;
    int rowBase = blockIdx.x * GBM;
    int lg = lane >> 2;
    int lt = lane & 3;

    if (t < FEAT) { sAs[t] = a_src[t]; sAd[t] = a_dst[t]; }

    float4 c[2][8];
#pragma unroll
    for (int mt = 0; mt < 2; mt++)
#pragma unroll
        for (int nt = 0; nt < 8; nt++) c[mt][nt] = make_float4(0.f, 0.f, 0.f, 0.f);

    int arow = t >> 3;             // 0..31 (+32*v)
    int acol = (t & 7) * 4;        // float col 0..28
    int bkp  = t >> 5;             // k-pair 0..7 (+8*v)

    for (int kk = 0; kk < FEAT; kk += GBK) {
        // A tile: 128x32 floats -> half2 pairs along k
#pragma unroll
        for (int v = 0; v < 4; v++) {
            int r = arow + v * 32;
            int gr = rowBase + r;
            float4 av = make_float4(0.f, 0.f, 0.f, 0.f);
            if (gr < N) av = *(const float4*)(A + (size_t)gr * FEAT + kk + acol);
            As[r][(acol >> 1) + 0] = pack_half2(av.x, av.y);
            As[r][(acol >> 1) + 1] = pack_half2(av.z, av.w);
        }
        // B tile: 32x128 floats -> pairs across adjacent k rows
#pragma unroll
        for (int v = 0; v < 2; v++) {
            int kp = bkp + v * 8;
            const float* w0 = W + (size_t)(kk + 2 * kp) * FEAT;
            const float* w1 = w0 + FEAT;
#pragma unroll
            for (int j = 0; j < 4; j++) {
                int col = lane + 32 * j;
                Bs[kp][col] = pack_half2(w0[col], w1[col]);
            }
        }
        __syncthreads();

#pragma unroll
        for (int ks = 0; ks < 2; ks++) {
            int k0h = ks * 8;   // k-pair offset
            uint32_t af[2][4];
#pragma unroll
            for (int mt = 0; mt < 2; mt++) {
                int row = wm * 32 + mt * 16 + lg;
                af[mt][0] = As[row][k0h + lt];
                af[mt][1] = As[row + 8][k0h + lt];
                af[mt][2] = As[row][k0h + lt + 4];
                af[mt][3] = As[row + 8][k0h + lt + 4];
            }
            uint32_t bf[8][2];
#pragma unroll
            for (int nt = 0; nt < 8; nt++) {
                int col = wn * 64 + nt * 8 + lg;
                bf[nt][0] = Bs[k0h + lt][col];
                bf[nt][1] = Bs[k0h + lt + 4][col];
            }
#pragma unroll
            for (int mt = 0; mt < 2; mt++)
#pragma unroll
                for (int nt = 0; nt < 8; nt++)
                    mma_f16(c[mt][nt], af[mt], bf[nt]);
        }
        __syncthreads();
    }

    // epilogue: fp16 store + fused score partials from fp32 accumulators
#pragma unroll
    for (int mt = 0; mt < 2; mt++) {
        int rl0 = wm * 32 + mt * 16 + lg;
        int row0 = rowBase + rl0;
        float pS0 = 0.f, pS8 = 0.f, pD0 = 0.f, pD8 = 0.f;
#pragma unroll
        for (int nt = 0; nt < 8; nt++) {
            int col = wn * 64 + nt * 8 + lt * 2;
            float as0 = sAs[col], as1 = sAs[col + 1];
            float ad0 = sAd[col], ad1 = sAd[col + 1];
            pS0 += c[mt][nt].x * as0 + c[mt][nt].y * as1;
            pD0 += c[mt][nt].x * ad0 + c[mt][nt].y * ad1;
            pS8 += c[mt][nt].z * as0 + c[mt][nt].w * as1;
            pD8 += c[mt][nt].z * ad0 + c[mt][nt].w * ad1;
            if (row0 < N)
                *(__half2*)(H16 + (size_t)row0 * FEAT + col) = __floats2half2_rn(c[mt][nt].x, c[mt][nt].y);
            if (row0 + 8 < N)
                *(__half2*)(H16 + (size_t)(row0 + 8) * FEAT + col) = __floats2half2_rn(c[mt][nt].z, c[mt][nt].w);
        }
#pragma unroll
        for (int o = 1; o < 4; o <<= 1) {
            pS0 += __shfl_xor_sync(0xffffffffu, pS0, o);
            pS8 += __shfl_xor_sync(0xffffffffu, pS8, o);
            pD0 += __shfl_xor_sync(0xffffffffu, pD0, o);
            pD8 += __shfl_xor_sync(0xffffffffu, pD8, o);
        }
        if (lt == 0) {
            redS[rl0][wn] = pS0;      redD[rl0][wn] = pD0;
            redS[rl0 + 8][wn] = pS8;  redD[rl0 + 8][wn] = pD8;
        }
    }
    __syncthreads();
    if (t < GBM) {
        int grow = rowBase + t;
        if (grow < N) {
            float s1 = redS[t][0] + redS[t][1];
            float s2 = redD[t][0] + redD[t][1];
            g_ssrc[grow] = s1;
            g_sdst[grow] = s2;
            float e = s1 + s2;
            g_es[grow] = e > 0.f ? e : 0.2f * e;
        }
    }
}

// Final GEMM: L[N,64] = (A1+A2)[N,128] @ W[128,64] + bl   (fp16 HMMA)
__global__ void __launch_bounds__(256, 2)
gemm_f16_final(const float* __restrict__ A1, const float* __restrict__ A2,
               const float* __restrict__ W, const float* __restrict__ bl,
               float* __restrict__ L, int N) {
    __shared__ uint32_t As[GBM][ASTR];
    __shared__ uint32_t Bs[GBK / 2][BSTRF];

    int t = threadIdx.x;
    int wid = t >> 5, lane = t & 31;
    int wm = wid >> 1, wn = wid & 1;
    int rowBase = blockIdx.x * GBM;
    int lg = lane >> 2;
    int lt = lane & 3;

    float4 c[2][4];
#pragma unroll
    for (int mt = 0; mt < 2; mt++)
#pragma unroll
        for (int nt = 0; nt < 4; nt++) c[mt][nt] = make_float4(0.f, 0.f, 0.f, 0.f);

    int arow = t >> 3;
    int acol = (t & 7) * 4;
    int bkp  = t >> 4;            // 0..15 k-pairs
    int bl16 = t & 15;            // 0..15

    for (int kk = 0; kk < FEAT; kk += GBK) {
#pragma unroll
        for (int v = 0; v < 4; v++) {
            int r = arow + v * 32;
            int gr = rowBase + r;
            float4 av = make_float4(0.f, 0.f, 0.f, 0.f);
            if (gr < N) {
                float4 a = *(const float4*)(A1 + (size_t)gr * FEAT + kk + acol);
                float4 b = *(const float4*)(A2 + (size_t)gr * FEAT + kk + acol);
                av = make_float4(a.x + b.x, a.y + b.y, a.z + b.z, a.w + b.w);
            }
            As[r][(acol >> 1) + 0] = pack_half2(av.x, av.y);
            As[r][(acol >> 1) + 1] = pack_half2(av.z, av.w);
        }
        {
            const float* w0 = W + (size_t)(kk + 2 * bkp) * COUT;
            const float* w1 = w0 + COUT;
#pragma unroll
            for (int j = 0; j < 4; j++) {
                int col = bl16 + 16 * j;
                Bs[bkp][col] = pack_half2(w0[col], w1[col]);
            }
        }
        __syncthreads();

#pragma unroll
        for (int ks = 0; ks < 2; ks++) {
            int k0h = ks * 8;
            uint32_t af[2][4];
#pragma unroll
            for (int mt = 0; mt < 2; mt++) {
                int row = wm * 32 + mt * 16 + lg;
                af[mt][0] = As[row][k0h + lt];
                af[mt][1] = As[row + 8][k0h + lt];
                af[mt][2] = As[row][k0h + lt + 4];
                af[mt][3] = As[row + 8][k0h + lt + 4];
            }
            uint32_t bf[4][2];
#pragma unroll
            for (int nt = 0; nt < 4; nt++) {
                int col = wn * 32 + nt * 8 + lg;
                bf[nt][0] = Bs[k0h + lt][col];
                bf[nt][1] = Bs[k0h + lt + 4][col];
            }
#pragma unroll
            for (int mt = 0; mt < 2; mt++)
#pragma unroll
                for (int nt = 0; nt < 4; nt++)
                    mma_f16(c[mt][nt], af[mt], bf[nt]);
        }
        __syncthreads();
    }

#pragma unroll
    for (int mt = 0; mt < 2; mt++) {
        int row0 = rowBase + wm * 32 + mt * 16 + lg;
#pragma unroll
        for (int nt = 0; nt < 4; nt++) {
            int col = wn * 32 + nt * 8 + lt * 2;
            float b0 = bl[col], b1 = bl[col + 1];
            if (row0 < N)
                *(float2*)(L + (size_t)row0 * COUT + col) = make_float2(c[mt][nt].x + b0, c[mt][nt].y + b1);
            if (row0 + 8 < N)
                *(float2*)(L + (size_t)(row0 + 8) * COUT + col) = make_float2(c[mt][nt].z + b0, c[mt][nt].w + b1);
        }
    }
}

// ---------------------------------------------------------------------------
// Fused per-node GAT: online softmax + fp16 aggregation. Warp per node.
// ---------------------------------------------------------------------------
__global__ void node_gat(const __half* __restrict__ h16,
                         const float* __restrict__ bias,
                         float* __restrict__ out, int N, int do_relu) {
    int d = (blockIdx.x * blockDim.x + threadIdx.x) >> 5;
    int lane = threadIdx.x & 31;
    if (d >= N) return;

    int beg = g_rowptr[d];
    int end = g_rowptr[d + 1];
    float sdst_d = g_sdst[d];
    float eself = g_es[d];

    // pass A: online (max, denom) + cache edge logits
    float m = LOWF;
    float den = 0.f;
    for (int j = beg + lane; j < end; j += 32) {
        float e = g_ssrc[g_csr_src[j]] + sdst_d;
        e = e > 0.f ? e : 0.2f * e;
        g_ew[j] = e;
        if (e > m) { den = den * __expf(m - e) + 1.f; m = e; }
        else        den += __expf(e - m);
    }
#pragma unroll
    for (int o = 16; o; o >>= 1) {
        float mo = __shfl_xor_sync(0xffffffffu, m, o);
        float dn = __shfl_xor_sync(0xffffffffu, den, o);
        float M = fmaxf(m, mo);
        den = den * __expf(m - M) + dn * __expf(mo - M);
        m = M;
    }
    {
        float M = fmaxf(m, eself);
        den = den * __expf(m - M) + __expf(eself - M);
        m = M;
    }
    float invden = 1.f / den;

    // pass B: aggregation (fp16 gathers, fp32 accum)
    float4 bv = ((const float4*)bias)[lane];
    uint2 us = *(const uint2*)(h16 + (size_t)d * FEAT + lane * 4);
    float2 s0 = __half22float2(*(__half2*)&us.x);
    float2 s1 = __half22float2(*(__half2*)&us.y);
    float a0 = __expf(eself - m) * invden;
    float4 acc;
    acc.x = fmaf(a0, s0.x, bv.x);
    acc.y = fmaf(a0, s0.y, bv.y);
    acc.z = fmaf(a0, s1.x, bv.z);
    acc.w = fmaf(a0, s1.y, bv.w);

#pragma unroll 4
    for (int j = beg; j < end; j++) {
        int s = g_csr_src[j];
        float a = __expf(g_ew[j] - m) * invden;
        uint2 u = *(const uint2*)(h16 + (size_t)s * FEAT + lane * 4);
        float2 f0 = __half22float2(*(__half2*)&u.x);
        float2 f1 = __half22float2(*(__half2*)&u.y);
        acc.x = fmaf(a, f0.x, acc.x);
        acc.y = fmaf(a, f0.y, acc.y);
        acc.z = fmaf(a, f1.x, acc.z);
        acc.w = fmaf(a, f1.y, acc.w);
    }

    if (do_relu) {
        acc.x = fmaxf(acc.x, 0.f);
        acc.y = fmaxf(acc.y, 0.f);
        acc.z = fmaxf(acc.z, 0.f);
        acc.w = fmaxf(acc.w, 0.f);
    }
    *(float4*)(out + (size_t)d * FEAT + lane * 4) = acc;
}

// ---------------------------------------------------------------------------
// Row log-softmax over logits [N, 64] (warp per row)
// ---------------------------------------------------------------------------
__global__ void logsoftmax_kernel(const float* __restrict__ L, float* __restrict__ out, int N) {
    int row = (blockIdx.x * blockDim.x + threadIdx.x) >> 5;
    int lane = threadIdx.x & 31;
    if (row >= N) return;
    float v0 = L[(size_t)row * COUT + lane];
    float v1 = L[(size_t)row * COUT + lane + 32];
    float m = fmaxf(v0, v1);
#pragma unroll
    for (int o = 16; o; o >>= 1) m = fmaxf(m, __shfl_xor_sync(0xffffffffu, m, o));
    float s = expf(v0 - m) + expf(v1 - m);
#pragma unroll
    for (int o = 16; o; o >>= 1) s += __shfl_xor_sync(0xffffffffu, s, o);
    float ls = m + logf(s);
    out[(size_t)row * COUT + lane]      = v0 - ls;
    out[(size_t)row * COUT + lane + 32] = v1 - ls;
}

__global__ void copy_edges_float(const void* ei, float* o, int n) {
    int i = blockIdx.x * blockDim.x + threadIdx.x;
    if (i >= n) return;
    long long v = g_is64 ? ((const long long*)ei)[i]
                         : (long long)((const int*)ei)[i];
    o[i] = (float)v;
}

// ---------------------------------------------------------------------------
// Host orchestration
// ---------------------------------------------------------------------------
extern "C" void kernel_launch(void* const* d_in, const int* in_sizes, int n_in,
                              void* d_out, int out_size) {
    const float* x   = (const float*)d_in[0];
    const void*  ei  = d_in[1];
    const float* W1  = (const float*)d_in[2];
    const float* a1s = (const float*)d_in[3];
    const float* a1d = (const float*)d_in[4];
    const float* b1  = (const float*)d_in[5];
    const float* W2  = (const float*)d_in[6];
    const float* a2s = (const float*)d_in[7];
    const float* a2d = (const float*)d_in[8];
    const float* b2  = (const float*)d_in[9];
    const float* Wl  = (const float*)d_in[10];
    const float* bl  = (const float*)d_in[11];

    int N = in_sizes[0] / FEAT;
    int E = in_sizes[1] / 2;

    float *h, *o1, *o2;
    __half* h16;
    void* pdeg; void* pfill;
    cudaGetSymbolAddress((void**)&h,   g_h);
    cudaGetSymbolAddress((void**)&h16, g_h16);
    cudaGetSymbolAddress((void**)&o1,  g_o1);
    cudaGetSymbolAddress((void**)&o2,  g_o2);
    cudaGetSymbolAddress(&pdeg,  g_deg);
    cudaGetSymbolAddress(&pfill, g_fill);

    // edge normalization + CSR build
    int ncheck = (2 * E < 2048) ? 2 * E : 2048;
    detect_kernel<<<1, 1024>>>(ei, ncheck, N);
    cudaMemsetAsync(pdeg,  0, (size_t)N * sizeof(int));
    cudaMemsetAsync(pfill, 0, (size_t)N * sizeof(int));
    convert_count<<<(2 * E + 255) / 256, 256>>>(ei, E);
    int nb = (N + SCAN_B - 1) / SCAN_B;
    scan_blocks<<<nb, SCAN_B>>>(N);
    scan_bsums<<<1, 256>>>(nb);
    add_offsets<<<(N + 255) / 256, 256>>>(N, E);
    csr_fill<<<(E + 255) / 256, 256>>>(E);

    int ggrid = (N + GBM - 1) / GBM;

    // layer 1: o1 = relu(gat(x))
    gemm_f16<<<ggrid, 256>>>(x, W1, a1s, a1d, h16, N);
    node_gat<<<(N * 32 + 255) / 256, 256>>>(h16, b1, o1, N, 1);

    // layer 2: o2 = gat(o1)
    gemm_f16<<<ggrid, 256>>>(o1, W2, a2s, a2d, h16, N);
    node_gat<<<(N * 32 + 255) / 256, 256>>>(h16, b2, o2, N, 0);

    // final: log_softmax((o1 + o2) @ Wl + bl)
    gemm_f16_final<<<ggrid, 256>>>(o1, o2, Wl, bl, h, N);
    logsoftmax_kernel<<<(N * 32 + 255) / 256, 256>>>(h, (float*)d_out, N);

    long long extra = (long long)out_size - (long long)N * COUT;
    if (extra == 2LL * E) {
        copy_edges_float<<<(2 * E + 255) / 256, 256>>>(ei, (float*)d_out + (size_t)N * COUT, 2 * E);
    } else if (extra == 4LL * E) {
        cudaMemcpyAsync((char*)d_out + (size_t)N * COUT * sizeof(float), ei,
                        sizeof(long long) * 2 * E, cudaMemcpyDeviceToDevice);
    }
}